// round 6
// baseline (speedup 1.0000x reference)
#include <cuda_runtime.h>
#include <cuda_bf16.h>
#include <math.h>

#define DD 128
#define N0CAP 100000
#define N1CAP 50000
#define N2CAP 50000
#define E1CAP 1600000
#define E2CAP 1600000
#define E12CAP 800000

// ---------------- scratch: feature buffers ----------------
__device__ float g_net1 [N1CAP * DD];
__device__ float g_net2 [N2CAP * DD];
__device__ float g_net2b[N2CAP * DD];
__device__ float g_s1 [N0CAP * DD];
__device__ float g_s2 [N0CAP * DD];
__device__ float g_s12[N0CAP * DD];

// ---------------- CSR scratch ----------------
#define RP1   0
#define RP2   (RP1 + N1CAP + 1)
#define RPB1  (RP2 + N2CAP + 1)
#define RPC   (RPB1 + N0CAP + 1)
#define RPB2  (RPC + N2CAP + 1)
#define RPTOT (RPB2 + N0CAP + 1)
__device__ int g_rowptr[RPTOT];
__device__ int g_cursor[RPTOT];   // doubles as histogram

__device__ int   g_p1g [E1CAP];  __device__ float g_p1w [E1CAP];
__device__ int   g_p2g [E2CAP];  __device__ float g_p2w [E2CAP];
__device__ int   g_pb1g[E1CAP];
__device__ int   g_pcg [E12CAP];
__device__ int   g_pb2g[E2CAP];  __device__ float g_pb2w[E2CAP];

// ================= fused histogram (5 jobs, 1 launch) =================
struct HistJobs {
    const int* idx[5];
    int* hist[5];
    int E[5];
    int off[6];    // block offsets (cumulative)
};
__global__ void k_hist_all(HistJobs jobs)
{
    int j = 0;
#pragma unroll
    for (int u = 0; u < 4; u++) if ((int)blockIdx.x >= jobs.off[j + 1]) j++;
    int e = (blockIdx.x - jobs.off[j]) * blockDim.x + threadIdx.x;
    if (e < jobs.E[j]) atomicAdd(jobs.hist[j] + __ldg(jobs.idx[j] + e), 1);
}

// ================= fused exclusive scan over 5 segments =================
struct Seg5 { int off[5]; int n[5]; };
__global__ void k_scan5(int* __restrict__ rowptr_base, int* __restrict__ cur_base, Seg5 segs)
{
    __shared__ int wsum[32];
    int off = segs.off[blockIdx.x];
    int N   = segs.n[blockIdx.x];
    int* hist = cur_base + off;
    int* rp   = rowptr_base + off;

    int tid = threadIdx.x;                 // blockDim = 1024
    int per = (N + 1023) >> 10;
    int lo = tid * per; if (lo > N) lo = N;
    int hi = lo + per;  if (hi > N) hi = N;

    int sum = 0;
    for (int i = lo; i < hi; i++) sum += hist[i];

    int lane = tid & 31, wid = tid >> 5;
    int v = sum;
#pragma unroll
    for (int o = 1; o < 32; o <<= 1) {
        int t = __shfl_up_sync(0xffffffffu, v, o);
        if (lane >= o) v += t;
    }
    if (lane == 31) wsum[wid] = v;
    __syncthreads();
    if (wid == 0) {
        int s = wsum[lane];
#pragma unroll
        for (int o = 1; o < 32; o <<= 1) {
            int t = __shfl_up_sync(0xffffffffu, s, o);
            if (lane >= o) s += t;
        }
        wsum[lane] = s;
    }
    __syncthreads();
    int excl = (v - sum) + (wid ? wsum[wid - 1] : 0);

    int run = excl;
    for (int i = lo; i < hi; i++) {
        int c = hist[i];
        rp[i] = run;
        hist[i] = run;
        run += c;
    }
    if (tid == 1023) rp[N] = excl + sum;
}

// ================= fused binning (5 jobs, 1 launch) =================
struct BinJobs {
    const int*   sc[5];
    const int*   gi[5];
    const float* ew[5];   // nullable
    int*   cur[5];
    int*   pg[5];
    float* pw[5];         // nullable
    int E[5];
    int off[6];
};
__global__ void k_bin_all(BinJobs jobs)
{
    int j = 0;
#pragma unroll
    for (int u = 0; u < 4; u++) if ((int)blockIdx.x >= jobs.off[j + 1]) j++;
    int e = (blockIdx.x - jobs.off[j]) * blockDim.x + threadIdx.x;
    if (e >= jobs.E[j]) return;
    int b = __ldg(jobs.sc[j] + e);
    int p = atomicAdd(jobs.cur[j] + b, 1);
    jobs.pg[j][p] = __ldg(jobs.gi[j] + e);
    if (jobs.pw[j]) jobs.pw[j][p] = __ldg(jobs.ew[j] + e);
}

// ================= general gather (nullable pw / xb), 2 jobs per launch ==========
// out = mean(feat[pg]*pw over row)            if xb == null
// out = (mean + xb) * 0.5                     if xb != null
struct GJob {
    const float* feat;
    const int*   pg;
    const float* pw;     // nullable
    const int*   rp;
    const float* xb;     // nullable
    float* out;
    int N;
};
struct GJobs2 { GJob j[2]; int off[3]; };   // off in blocks

__global__ void k_gather2(GJobs2 jobs)
{
    int ji = ((int)blockIdx.x >= jobs.off[1]) ? 1 : 0;
    const GJob& J = jobs.j[ji];
    int wpb = blockDim.x >> 5;
    int n = (blockIdx.x - jobs.off[ji]) * wpb + (threadIdx.x >> 5);
    int lane = threadIdx.x & 31;
    if (n >= J.N) return;
    int start = __ldg(J.rp + n), end = __ldg(J.rp + n + 1);

    float4 acc = make_float4(0.f, 0.f, 0.f, 0.f);
    const int* pg = J.pg;
    const float* pw = J.pw;
    const float* feat = J.feat;
    int j = start;
    for (; j + 4 <= end; j += 4) {
        int g0 = __ldg(pg + j), g1 = __ldg(pg + j + 1);
        int g2 = __ldg(pg + j + 2), g3 = __ldg(pg + j + 3);
        float w0 = 1.f, w1 = 1.f, w2 = 1.f, w3 = 1.f;
        if (pw) { w0 = __ldg(pw + j); w1 = __ldg(pw + j + 1);
                  w2 = __ldg(pw + j + 2); w3 = __ldg(pw + j + 3); }
        float4 v0 = __ldg((const float4*)(feat + (size_t)g0 * DD) + lane);
        float4 v1 = __ldg((const float4*)(feat + (size_t)g1 * DD) + lane);
        float4 v2 = __ldg((const float4*)(feat + (size_t)g2 * DD) + lane);
        float4 v3 = __ldg((const float4*)(feat + (size_t)g3 * DD) + lane);
        acc.x += v0.x * w0 + v1.x * w1 + v2.x * w2 + v3.x * w3;
        acc.y += v0.y * w0 + v1.y * w1 + v2.y * w2 + v3.y * w3;
        acc.z += v0.z * w0 + v1.z * w1 + v2.z * w2 + v3.z * w3;
        acc.w += v0.w * w0 + v1.w * w1 + v2.w * w2 + v3.w * w3;
    }
    for (; j < end; j++) {
        int g = __ldg(pg + j);
        float w = pw ? __ldg(pw + j) : 1.f;
        float4 v = __ldg((const float4*)(feat + (size_t)g * DD) + lane);
        acc.x += v.x * w; acc.y += v.y * w; acc.z += v.z * w; acc.w += v.w * w;
    }
    int deg = end - start;
    float inv = 1.0f / (deg > 1 ? (float)deg : 1.0f);
    float4 o;
    if (J.xb) {
        float4 x = __ldg((const float4*)(J.xb + (size_t)n * DD) + lane);
        o.x = (acc.x * inv + x.x) * 0.5f;
        o.y = (acc.y * inv + x.y) * 0.5f;
        o.z = (acc.z * inv + x.z) * 0.5f;
        o.w = (acc.w * inv + x.w) * 0.5f;
    } else {
        o = make_float4(acc.x * inv, acc.y * inv, acc.z * inv, acc.w * inv);
    }
    ((float4*)(J.out + (size_t)n * DD))[lane] = o;
}

// ================= dual gather over shared CSR =================
__global__ void k_gather_dual(const float* __restrict__ feat_a,
                              const float* __restrict__ feat_b,
                              const int*   __restrict__ pg,
                              const float* __restrict__ pw,
                              const int*   __restrict__ rp,
                              float* __restrict__ out_a,
                              float* __restrict__ out_b,
                              int N)
{
    int t = blockIdx.x * blockDim.x + threadIdx.x;
    int n = t >> 5, lane = t & 31;
    if (n >= N) return;
    int start = __ldg(rp + n), end = __ldg(rp + n + 1);

    float4 aa = make_float4(0.f, 0.f, 0.f, 0.f);
    float4 ab = make_float4(0.f, 0.f, 0.f, 0.f);
    int j = start;
    for (; j + 2 <= end; j += 2) {
        int g0 = __ldg(pg + j), g1 = __ldg(pg + j + 1);
        float w0 = __ldg(pw + j), w1 = __ldg(pw + j + 1);
        float4 a0 = __ldg((const float4*)(feat_a + (size_t)g0 * DD) + lane);
        float4 b0 = __ldg((const float4*)(feat_b + (size_t)g0 * DD) + lane);
        float4 a1 = __ldg((const float4*)(feat_a + (size_t)g1 * DD) + lane);
        float4 b1 = __ldg((const float4*)(feat_b + (size_t)g1 * DD) + lane);
        aa.x += a0.x + a1.x; aa.y += a0.y + a1.y; aa.z += a0.z + a1.z; aa.w += a0.w + a1.w;
        ab.x += b0.x * w0 + b1.x * w1; ab.y += b0.y * w0 + b1.y * w1;
        ab.z += b0.z * w0 + b1.z * w1; ab.w += b0.w * w0 + b1.w * w1;
    }
    for (; j < end; j++) {
        int g = __ldg(pg + j);
        float w = __ldg(pw + j);
        float4 a = __ldg((const float4*)(feat_a + (size_t)g * DD) + lane);
        float4 b = __ldg((const float4*)(feat_b + (size_t)g * DD) + lane);
        aa.x += a.x; aa.y += a.y; aa.z += a.z; aa.w += a.w;
        ab.x += b.x * w; ab.y += b.y * w; ab.z += b.z * w; ab.w += b.w * w;
    }
    int deg = end - start;
    float inv = 1.0f / (deg > 1 ? (float)deg : 1.0f);
    float4 oa = make_float4(aa.x * inv, aa.y * inv, aa.z * inv, aa.w * inv);
    float4 ob = make_float4(ab.x * inv, ab.y * inv, ab.z * inv, ab.w * inv);
    ((float4*)(out_a + (size_t)n * DD))[lane] = oa;
    ((float4*)(out_b + (size_t)n * DD))[lane] = ob;
}

// ================= fused GEMM x3: y = relu(x @ W^T + b), in place =================
#define GEMM_SMEM (64 * 128 * 4 + 129 * 128 * 4)

__device__ __forceinline__ void ffma2(unsigned long long& d, unsigned long long a,
                                      unsigned long long b) {
    asm("fma.rn.f32x2 %0, %1, %2, %0;" : "+l"(d) : "l"(a), "l"(b));
}
__device__ __forceinline__ unsigned long long pack2(float lo, float hi) {
    unsigned long long r;
    asm("mov.b64 %0, {%1, %2};" : "=l"(r) : "f"(lo), "f"(hi));
    return r;
}
__device__ __forceinline__ void unpack2(unsigned long long v, float& lo, float& hi) {
    asm("mov.b64 {%0, %1}, %2;" : "=f"(lo), "=f"(hi) : "l"(v));
}

struct GemmJobs {
    float* x[3];
    const float* W[3];
    const float* b[3];
    int N;
};

__global__ void k_gemm_relu3(GemmJobs jobs)
{
    extern __shared__ float sm[];
    float* xs = sm;              // [64][128]
    float* ws = sm + 64 * 128;   // [128][129] transposed W
    int tx = threadIdx.x, ty = threadIdx.y;
    int tid = ty * 32 + tx;
    int row0 = blockIdx.x * 64;
    int jz = blockIdx.y;
    float* xio = jobs.x[jz];
    const float* W = jobs.W[jz];
    const float* bias = jobs.b[jz];
    int N = jobs.N;

    for (int idx = tid; idx < 128 * 128; idx += 256) {
        int i = idx >> 7, k = idx & 127;
        ws[k * 129 + i] = __ldg(W + idx);
    }
    for (int idx = tid; idx < 64 * 32; idx += 256) {
        int r = idx >> 5;
        int row = row0 + r;
        float4 v = make_float4(0.f, 0.f, 0.f, 0.f);
        if (row < N) v = ((const float4*)(xio + (size_t)row * DD))[idx & 31];
        ((float4*)xs)[idx] = v;
    }
    __syncthreads();

    unsigned long long accA[8], accB[8];
#pragma unroll
    for (int r = 0; r < 8; r++) { accA[r] = 0ull; accB[r] = 0ull; }

#pragma unroll 4
    for (int k = 0; k < 128; k++) {
        float b0 = ws[k * 129 + tx];
        float b1 = ws[k * 129 + tx + 32];
        float b2 = ws[k * 129 + tx + 64];
        float b3 = ws[k * 129 + tx + 96];
        unsigned long long bA = pack2(b0, b1);
        unsigned long long bB = pack2(b2, b3);
#pragma unroll
        for (int r = 0; r < 8; r++) {
            float a = xs[(ty * 8 + r) * 128 + k];
            unsigned long long aa = pack2(a, a);
            ffma2(accA[r], aa, bA);
            ffma2(accB[r], aa, bB);
        }
    }

    float bb0 = __ldg(bias + tx);
    float bb1 = __ldg(bias + tx + 32);
    float bb2 = __ldg(bias + tx + 64);
    float bb3 = __ldg(bias + tx + 96);
#pragma unroll
    for (int r = 0; r < 8; r++) {
        int row = row0 + ty * 8 + r;
        if (row < N) {
            float a0, a1, a2, a3;
            unpack2(accA[r], a0, a1);
            unpack2(accB[r], a2, a3);
            float* yr = xio + (size_t)row * DD;
            yr[tx]      = fmaxf(a0 + bb0, 0.f);
            yr[tx + 32] = fmaxf(a1 + bb1, 0.f);
            yr[tx + 64] = fmaxf(a2 + bb2, 0.f);
            yr[tx + 96] = fmaxf(a3 + bb3, 0.f);
        }
    }
}

// ================= attention combine =================
__global__ void k_att(const float* __restrict__ y1,
                      const float* __restrict__ y2,
                      const float* __restrict__ y3,
                      const float* __restrict__ att,
                      float* __restrict__ out,
                      int N)
{
    int t = blockIdx.x * blockDim.x + threadIdx.x;
    int n = t >> 5, lane = t & 31;
    if (n >= N) return;
    size_t base = (size_t)n * DD;
    float4 v1 = __ldg((const float4*)(y1 + base) + lane);
    float4 v2 = __ldg((const float4*)(y2 + base) + lane);
    float4 v3 = __ldg((const float4*)(y3 + base) + lane);
    float4 a1 = __ldg((const float4*)att + lane);
    float4 a2 = __ldg((const float4*)att + 32 + lane);
    float4 a3 = __ldg((const float4*)att + 64 + lane);

    float s1 = v1.x * a1.x + v1.y * a1.y + v1.z * a1.z + v1.w * a1.w;
    float s2 = v2.x * a2.x + v2.y * a2.y + v2.z * a2.z + v2.w * a2.w;
    float s3 = v3.x * a3.x + v3.y * a3.y + v3.z * a3.z + v3.w * a3.w;
#pragma unroll
    for (int off = 16; off; off >>= 1) {
        s1 += __shfl_xor_sync(0xFFFFFFFFu, s1, off);
        s2 += __shfl_xor_sync(0xFFFFFFFFu, s2, off);
        s3 += __shfl_xor_sync(0xFFFFFFFFu, s3, off);
    }
    float m = fmaxf(s1, fmaxf(s2, s3));
    float e1 = __expf(s1 - m), e2 = __expf(s2 - m), e3 = __expf(s3 - m);
    float inv = 1.0f / (e1 + e2 + e3);
    float w1 = e1 * inv, w2 = e2 * inv, w3 = e3 * inv;

    float4 o;
    o.x = w1 * v1.x + w2 * v2.x + w3 * v3.x;
    o.y = w1 * v1.y + w2 * v2.y + w3 * v3.y;
    o.z = w1 * v1.z + w2 * v2.z + w3 * v3.z;
    o.w = w1 * v1.w + w2 * v2.w + w3 * v3.w;
    ((float4*)(out + base))[lane] = o;
}

// ================= launch =================
static inline int cdiv(long long a, int b) { return (int)((a + b - 1) / b); }

extern "C" void kernel_launch(void* const* d_in, const int* in_sizes, int n_in,
                              void* d_out, int out_size)
{
    const float* x_node   = (const float*)d_in[0];
    const float* x1       = (const float*)d_in[1];
    const float* x2       = (const float*)d_in[2];
    const int*   ei1_src  = (const int*)d_in[3];
    const int*   ei1_dst  = (const int*)d_in[4];
    const int*   ei2_src  = (const int*)d_in[5];
    const int*   ei2_dst  = (const int*)d_in[6];
    const int*   ei12_src = (const int*)d_in[7];
    const int*   ei12_dst = (const int*)d_in[8];
    const float* ew1      = (const float*)d_in[9];
    const float* ew2      = (const float*)d_in[10];
    const float* W1       = (const float*)d_in[11];
    const float* b1       = (const float*)d_in[12];
    const float* W2       = (const float*)d_in[13];
    const float* b2       = (const float*)d_in[14];
    const float* W12      = (const float*)d_in[15];
    const float* b12      = (const float*)d_in[16];
    const float* att      = (const float*)d_in[17];
    float* out = (float*)d_out;

    int n0  = in_sizes[0] / DD;
    int n1  = in_sizes[1] / DD;
    int n2  = in_sizes[2] / DD;
    int e1  = in_sizes[3];
    int e2  = in_sizes[5];
    int e12 = in_sizes[7];

    float *net1, *net2, *net2b, *s1, *s2, *s12;
    int *rowptr, *cursor;
    int *p1g, *p2g, *pb1g, *pcg, *pb2g;
    float *p1w, *p2w, *pb2w;
    cudaGetSymbolAddress((void**)&net1,  g_net1);
    cudaGetSymbolAddress((void**)&net2,  g_net2);
    cudaGetSymbolAddress((void**)&net2b, g_net2b);
    cudaGetSymbolAddress((void**)&s1,  g_s1);
    cudaGetSymbolAddress((void**)&s2,  g_s2);
    cudaGetSymbolAddress((void**)&s12, g_s12);
    cudaGetSymbolAddress((void**)&rowptr, g_rowptr);
    cudaGetSymbolAddress((void**)&cursor, g_cursor);
    cudaGetSymbolAddress((void**)&p1g,  g_p1g);
    cudaGetSymbolAddress((void**)&p1w,  g_p1w);
    cudaGetSymbolAddress((void**)&p2g,  g_p2g);
    cudaGetSymbolAddress((void**)&p2w,  g_p2w);
    cudaGetSymbolAddress((void**)&pb1g, g_pb1g);
    cudaGetSymbolAddress((void**)&pcg,  g_pcg);
    cudaGetSymbolAddress((void**)&pb2g, g_pb2g);
    cudaGetSymbolAddress((void**)&pb2w, g_pb2w);

    cudaFuncSetAttribute(k_gemm_relu3, cudaFuncAttributeMaxDynamicSharedMemorySize, GEMM_SMEM);

    cudaMemsetAsync(cursor, 0, (size_t)RPTOT * sizeof(int), 0);

    const int BT = 256;

    // --- fused histograms (5 jobs) ---
    {
        HistJobs hj;
        const int* idxs[5] = { ei1_dst, ei2_dst, ei1_src, ei12_dst, ei2_src };
        int histo[5] = { RP1, RP2, RPB1, RPC, RPB2 };
        int Es[5]    = { e1, e2, e1, e12, e2 };
        int off = 0;
        for (int j = 0; j < 5; j++) {
            hj.idx[j] = idxs[j];
            hj.hist[j] = cursor + histo[j];
            hj.E[j] = Es[j];
            hj.off[j] = off;
            off += cdiv(Es[j], BT);
        }
        hj.off[5] = off;
        k_hist_all<<<off, BT>>>(hj);
    }

    // --- fused scans (5 blocks) ---
    {
        Seg5 segs;
        segs.off[0] = RP1;  segs.n[0] = n1;
        segs.off[1] = RP2;  segs.n[1] = n2;
        segs.off[2] = RPB1; segs.n[2] = n0;
        segs.off[3] = RPC;  segs.n[3] = n2;
        segs.off[4] = RPB2; segs.n[4] = n0;
        k_scan5<<<5, 1024>>>(rowptr, cursor, segs);
    }

    // --- fused binning (5 jobs) ---
    {
        BinJobs bj;
        const int* scs[5]   = { ei1_dst, ei2_dst, ei1_src, ei12_dst, ei2_src };
        const int* gis[5]   = { ei1_src, ei2_src, ei1_dst, ei12_src, ei2_dst };
        const float* ews[5] = { ew1, ew2, 0, 0, ew2 };
        int curo[5]  = { RP1, RP2, RPB1, RPC, RPB2 };
        int* pgs[5]  = { p1g, p2g, pb1g, pcg, pb2g };
        float* pws[5]= { p1w, p2w, 0, 0, pb2w };
        int Es[5]    = { e1, e2, e1, e12, e2 };
        int off = 0;
        for (int j = 0; j < 5; j++) {
            bj.sc[j] = scs[j]; bj.gi[j] = gis[j]; bj.ew[j] = ews[j];
            bj.cur[j] = cursor + curo[j]; bj.pg[j] = pgs[j]; bj.pw[j] = pws[j];
            bj.E[j] = Es[j];
            bj.off[j] = off;
            off += cdiv(Es[j], BT);
        }
        bj.off[5] = off;
        k_bin_all<<<off, BT>>>(bj);
    }

    const int WPB = BT / 32;

    // --- gather level A: net1, net2 (independent) ---
    {
        GJobs2 gj;
        gj.j[0] = { x_node, p1g, p1w, rowptr + RP1, x1, net1, n1 };
        gj.j[1] = { x_node, p2g, p2w, rowptr + RP2, x2, net2, n2 };
        gj.off[0] = 0;
        gj.off[1] = cdiv(n1, WPB);
        gj.off[2] = gj.off[1] + cdiv(n2, WPB);
        k_gather2<<<gj.off[2], BT>>>(gj);
    }

    // --- gather level B: s1 (mean only), net2b (msg) — both read net1 ---
    {
        GJobs2 gj;
        gj.j[0] = { net1, pb1g, 0, rowptr + RPB1, 0,  s1,    n0 };
        gj.j[1] = { net1, pcg,  0, rowptr + RPC,  x2, net2b, n2 };
        gj.off[0] = 0;
        gj.off[1] = cdiv(n0, WPB);
        gj.off[2] = gj.off[1] + cdiv(n2, WPB);
        k_gather2<<<gj.off[2], BT>>>(gj);
    }

    // --- dual gather: s2, s12 ---
    k_gather_dual<<<cdiv((long long)n0 * 32, BT), BT>>>(net2, net2b, pb2g, pb2w,
                                                        rowptr + RPB2, s2, s12, n0);

    // --- fused GEMM x3 ---
    {
        GemmJobs gm;
        gm.x[0] = s1;  gm.W[0] = W1;  gm.b[0] = b1;
        gm.x[1] = s2;  gm.W[1] = W2;  gm.b[1] = b2;
        gm.x[2] = s12; gm.W[2] = W12; gm.b[2] = b12;
        gm.N = n0;
        dim3 grid(cdiv(n0, 64), 3);
        dim3 blk(32, 8);
        k_gemm_relu3<<<grid, blk, GEMM_SMEM>>>(gm);
    }

    // --- attention combine ---
    k_att<<<cdiv((long long)n0 * 32, BT), BT>>>(s1, s2, s12, att, out, n0);
}

// round 7
// speedup vs baseline: 1.0980x; 1.0980x over previous
#include <cuda_runtime.h>
#include <cuda_bf16.h>
#include <math.h>

#define DD 128
#define N0CAP 100000
#define N1CAP 50000
#define N2CAP 50000
#define E1CAP 1600000
#define E2CAP 1600000
#define E12CAP 800000

// ---------------- scratch: feature buffers ----------------
__device__ float g_net1 [N1CAP * DD];
__device__ float g_net2 [N2CAP * DD];
__device__ float g_net2b[N2CAP * DD];
__device__ float g_s1 [N0CAP * DD];
__device__ float g_s2 [N0CAP * DD];
__device__ float g_s12[N0CAP * DD];

// ---------------- CSR scratch ----------------
#define RP1   0
#define RP2   (RP1 + N1CAP + 1)
#define RPB1  (RP2 + N2CAP + 1)
#define RPC   (RPB1 + N0CAP + 1)
#define RPB2  (RPC + N2CAP + 1)
#define RPTOT (RPB2 + N0CAP + 1)
__device__ int g_rowptr[RPTOT];
__device__ int g_cursor[RPTOT];   // doubles as histogram

__device__ int   g_p1g [E1CAP];  __device__ float g_p1w [E1CAP];
__device__ int   g_p2g [E2CAP];  __device__ float g_p2w [E2CAP];
__device__ int   g_pb1g[E1CAP];
__device__ int   g_pcg [E12CAP];
__device__ int   g_pb2g[E2CAP];  __device__ float g_pb2w[E2CAP];

// ---------------- histogram ----------------
__global__ void k_hist(const int* __restrict__ idx, int* __restrict__ hist, int E)
{
    int e = blockIdx.x * blockDim.x + threadIdx.x;
    if (e < E) atomicAdd(hist + __ldg(idx + e), 1);
}

// ---------------- fused exclusive scan over 5 segments (one block each) ----------------
struct Seg5 { int off[5]; int n[5]; };
__global__ void k_scan5(int* __restrict__ rowptr_base, int* __restrict__ cur_base, Seg5 segs)
{
    __shared__ int wsum[32];
    int off = segs.off[blockIdx.x];
    int N   = segs.n[blockIdx.x];
    int* hist = cur_base + off;     // counts in, cursor (prefix) out
    int* rp   = rowptr_base + off;

    int tid = threadIdx.x;                 // blockDim = 1024
    int per = (N + 1023) >> 10;
    int lo = tid * per; if (lo > N) lo = N;
    int hi = lo + per;  if (hi > N) hi = N;

    int sum = 0;
    for (int i = lo; i < hi; i++) sum += hist[i];

    int lane = tid & 31, wid = tid >> 5;
    int v = sum;
#pragma unroll
    for (int o = 1; o < 32; o <<= 1) {
        int t = __shfl_up_sync(0xffffffffu, v, o);
        if (lane >= o) v += t;
    }
    if (lane == 31) wsum[wid] = v;
    __syncthreads();
    if (wid == 0) {
        int s = wsum[lane];
#pragma unroll
        for (int o = 1; o < 32; o <<= 1) {
            int t = __shfl_up_sync(0xffffffffu, s, o);
            if (lane >= o) s += t;
        }
        wsum[lane] = s;
    }
    __syncthreads();
    int excl = (v - sum) + (wid ? wsum[wid - 1] : 0);

    int run = excl;
    for (int i = lo; i < hi; i++) {
        int c = hist[i];
        rp[i] = run;
        hist[i] = run;    // cursor = start position
        run += c;
    }
    if (tid == 1023) rp[N] = excl + sum;   // grand total
}

// ---------------- binning: perm[pos] = gather_idx (and weight) ----------------
__global__ void k_bin(const int*   __restrict__ sc_idx,
                      const int*   __restrict__ g_idx,
                      const float* __restrict__ ew,
                      int*  __restrict__ cursor,
                      int*  __restrict__ pg,
                      float* __restrict__ pw,
                      int E)
{
    int e = blockIdx.x * blockDim.x + threadIdx.x;
    if (e >= E) return;
    int b = __ldg(sc_idx + e);
    int p = atomicAdd(cursor + b, 1);
    pg[p] = __ldg(g_idx + e);
    if (pw) pw[p] = __ldg(ew + e);
}

// ---------------- gather with msg finalize: out = (mean + xb) * 0.5 ----------------
__global__ void k_gather_msg(const float* __restrict__ feat,
                             const int*   __restrict__ pg,
                             const float* __restrict__ pw,   // may be null (w=1)
                             const int*   __restrict__ rp,
                             const float* __restrict__ xb,
                             float* __restrict__ out,
                             int N)
{
    int t = blockIdx.x * blockDim.x + threadIdx.x;
    int n = t >> 5, lane = t & 31;
    if (n >= N) return;
    int start = __ldg(rp + n), end = __ldg(rp + n + 1);

    float4 acc = make_float4(0.f, 0.f, 0.f, 0.f);
    int j = start;
    for (; j + 4 <= end; j += 4) {
        int g0 = __ldg(pg + j), g1 = __ldg(pg + j + 1);
        int g2 = __ldg(pg + j + 2), g3 = __ldg(pg + j + 3);
        float w0 = 1.f, w1 = 1.f, w2 = 1.f, w3 = 1.f;
        if (pw) { w0 = __ldg(pw + j); w1 = __ldg(pw + j + 1);
                  w2 = __ldg(pw + j + 2); w3 = __ldg(pw + j + 3); }
        float4 v0 = __ldg((const float4*)(feat + (size_t)g0 * DD) + lane);
        float4 v1 = __ldg((const float4*)(feat + (size_t)g1 * DD) + lane);
        float4 v2 = __ldg((const float4*)(feat + (size_t)g2 * DD) + lane);
        float4 v3 = __ldg((const float4*)(feat + (size_t)g3 * DD) + lane);
        acc.x += v0.x * w0 + v1.x * w1 + v2.x * w2 + v3.x * w3;
        acc.y += v0.y * w0 + v1.y * w1 + v2.y * w2 + v3.y * w3;
        acc.z += v0.z * w0 + v1.z * w1 + v2.z * w2 + v3.z * w3;
        acc.w += v0.w * w0 + v1.w * w1 + v2.w * w2 + v3.w * w3;
    }
    for (; j < end; j++) {
        int g = __ldg(pg + j);
        float w = pw ? __ldg(pw + j) : 1.f;
        float4 v = __ldg((const float4*)(feat + (size_t)g * DD) + lane);
        acc.x += v.x * w; acc.y += v.y * w; acc.z += v.z * w; acc.w += v.w * w;
    }
    int deg = end - start;
    float inv = 1.0f / (deg > 1 ? (float)deg : 1.0f);
    float4 x = __ldg((const float4*)(xb + (size_t)n * DD) + lane);
    float4 o;
    o.x = (acc.x * inv + x.x) * 0.5f;
    o.y = (acc.y * inv + x.y) * 0.5f;
    o.z = (acc.z * inv + x.z) * 0.5f;
    o.w = (acc.w * inv + x.w) * 0.5f;
    ((float4*)(out + (size_t)n * DD))[lane] = o;
}

// ---------------- gather mean only: out = mean ----------------
__global__ void k_gather_s(const float* __restrict__ feat,
                           const int*   __restrict__ pg,
                           const int*   __restrict__ rp,
                           float* __restrict__ out,
                           int N)
{
    int t = blockIdx.x * blockDim.x + threadIdx.x;
    int n = t >> 5, lane = t & 31;
    if (n >= N) return;
    int start = __ldg(rp + n), end = __ldg(rp + n + 1);

    float4 acc = make_float4(0.f, 0.f, 0.f, 0.f);
    int j = start;
    for (; j + 4 <= end; j += 4) {
        int g0 = __ldg(pg + j), g1 = __ldg(pg + j + 1);
        int g2 = __ldg(pg + j + 2), g3 = __ldg(pg + j + 3);
        float4 v0 = __ldg((const float4*)(feat + (size_t)g0 * DD) + lane);
        float4 v1 = __ldg((const float4*)(feat + (size_t)g1 * DD) + lane);
        float4 v2 = __ldg((const float4*)(feat + (size_t)g2 * DD) + lane);
        float4 v3 = __ldg((const float4*)(feat + (size_t)g3 * DD) + lane);
        acc.x += v0.x + v1.x + v2.x + v3.x;
        acc.y += v0.y + v1.y + v2.y + v3.y;
        acc.z += v0.z + v1.z + v2.z + v3.z;
        acc.w += v0.w + v1.w + v2.w + v3.w;
    }
    for (; j < end; j++) {
        int g = __ldg(pg + j);
        float4 v = __ldg((const float4*)(feat + (size_t)g * DD) + lane);
        acc.x += v.x; acc.y += v.y; acc.z += v.z; acc.w += v.w;
    }
    int deg = end - start;
    float inv = 1.0f / (deg > 1 ? (float)deg : 1.0f);
    float4 o = make_float4(acc.x * inv, acc.y * inv, acc.z * inv, acc.w * inv);
    ((float4*)(out + (size_t)n * DD))[lane] = o;
}

// ---------------- dual gather over shared CSR: s2 (w=1) and s12 (w=ew) ----------------
__global__ void k_gather_dual(const float* __restrict__ feat_a,
                              const float* __restrict__ feat_b,
                              const int*   __restrict__ pg,
                              const float* __restrict__ pw,
                              const int*   __restrict__ rp,
                              float* __restrict__ out_a,
                              float* __restrict__ out_b,
                              int N)
{
    int t = blockIdx.x * blockDim.x + threadIdx.x;
    int n = t >> 5, lane = t & 31;
    if (n >= N) return;
    int start = __ldg(rp + n), end = __ldg(rp + n + 1);

    float4 aa = make_float4(0.f, 0.f, 0.f, 0.f);
    float4 ab = make_float4(0.f, 0.f, 0.f, 0.f);
    int j = start;
    for (; j + 2 <= end; j += 2) {
        int g0 = __ldg(pg + j), g1 = __ldg(pg + j + 1);
        float w0 = __ldg(pw + j), w1 = __ldg(pw + j + 1);
        float4 a0 = __ldg((const float4*)(feat_a + (size_t)g0 * DD) + lane);
        float4 b0 = __ldg((const float4*)(feat_b + (size_t)g0 * DD) + lane);
        float4 a1 = __ldg((const float4*)(feat_a + (size_t)g1 * DD) + lane);
        float4 b1 = __ldg((const float4*)(feat_b + (size_t)g1 * DD) + lane);
        aa.x += a0.x + a1.x; aa.y += a0.y + a1.y; aa.z += a0.z + a1.z; aa.w += a0.w + a1.w;
        ab.x += b0.x * w0 + b1.x * w1; ab.y += b0.y * w0 + b1.y * w1;
        ab.z += b0.z * w0 + b1.z * w1; ab.w += b0.w * w0 + b1.w * w1;
    }
    for (; j < end; j++) {
        int g = __ldg(pg + j);
        float w = __ldg(pw + j);
        float4 a = __ldg((const float4*)(feat_a + (size_t)g * DD) + lane);
        float4 b = __ldg((const float4*)(feat_b + (size_t)g * DD) + lane);
        aa.x += a.x; aa.y += a.y; aa.z += a.z; aa.w += a.w;
        ab.x += b.x * w; ab.y += b.y * w; ab.z += b.z * w; ab.w += b.w * w;
    }
    int deg = end - start;
    float inv = 1.0f / (deg > 1 ? (float)deg : 1.0f);
    float4 oa = make_float4(aa.x * inv, aa.y * inv, aa.z * inv, aa.w * inv);
    float4 ob = make_float4(ab.x * inv, ab.y * inv, ab.z * inv, ab.w * inv);
    ((float4*)(out_a + (size_t)n * DD))[lane] = oa;
    ((float4*)(out_b + (size_t)n * DD))[lane] = ob;
}

// ========== GEMM: y = relu(x @ W^T + b), in place, k-packed FFMA2 ==========
// smem: xs [64][128] (k contiguous), ws [128][132] row-major W (k contiguous, pitch 132)
// Per 4-k step: 8 LDS.128 (a, broadcast) + 4 LDS.128 (b, conflict-free) + 64 FFMA2.
#define WPITCH 132
#define GEMM_SMEM (64 * 128 * 4 + 128 * WPITCH * 4)

__device__ __forceinline__ void ffma2(unsigned long long& d, unsigned long long a,
                                      unsigned long long b) {
    asm("fma.rn.f32x2 %0, %1, %2, %0;" : "+l"(d) : "l"(a), "l"(b));
}
__device__ __forceinline__ void f4_to_u2(float4 v, unsigned long long& lo,
                                         unsigned long long& hi) {
    asm("mov.b64 %0, {%2, %3};\n\tmov.b64 %1, {%4, %5};"
        : "=l"(lo), "=l"(hi) : "f"(v.x), "f"(v.y), "f"(v.z), "f"(v.w));
}
__device__ __forceinline__ float u2_sum(unsigned long long v) {
    float lo, hi;
    asm("mov.b64 {%0, %1}, %2;" : "=f"(lo), "=f"(hi) : "l"(v));
    return lo + hi;
}

__global__ void __launch_bounds__(256, 1)
k_gemm_relu(float* __restrict__ xio,
            const float* __restrict__ W,
            const float* __restrict__ bias,
            int N)
{
    extern __shared__ float sm[];
    float* xs = sm;               // [64][128]
    float* ws = sm + 64 * 128;    // [128][WPITCH], row-major W
    int tx = threadIdx.x, ty = threadIdx.y;
    int tid = ty * 32 + tx;
    int row0 = blockIdx.x * 64;

    for (int idx = tid; idx < 128 * 128; idx += 256) {
        int i = idx >> 7, k = idx & 127;
        ws[i * WPITCH + k] = __ldg(W + idx);
    }
    for (int idx = tid; idx < 64 * 32; idx += 256) {
        int r = idx >> 5;
        int row = row0 + r;
        float4 v = make_float4(0.f, 0.f, 0.f, 0.f);
        if (row < N) v = ((const float4*)(xio + (size_t)row * DD))[idx & 31];
        ((float4*)xs)[idx] = v;
    }
    __syncthreads();

    unsigned long long acc[8][4];
#pragma unroll
    for (int r = 0; r < 8; r++)
#pragma unroll
        for (int c = 0; c < 4; c++) acc[r][c] = 0ull;

    const float* wr0 = ws + (size_t)tx * WPITCH;
    const float* wr1 = ws + (size_t)(tx + 32) * WPITCH;
    const float* wr2 = ws + (size_t)(tx + 64) * WPITCH;
    const float* wr3 = ws + (size_t)(tx + 96) * WPITCH;
    const float* xr  = xs + (size_t)(ty * 8) * 128;

#pragma unroll 4
    for (int k4 = 0; k4 < 32; k4++) {
        unsigned long long bl[4], bh[4];
        f4_to_u2(*(const float4*)(wr0 + k4 * 4), bl[0], bh[0]);
        f4_to_u2(*(const float4*)(wr1 + k4 * 4), bl[1], bh[1]);
        f4_to_u2(*(const float4*)(wr2 + k4 * 4), bl[2], bh[2]);
        f4_to_u2(*(const float4*)(wr3 + k4 * 4), bl[3], bh[3]);
#pragma unroll
        for (int r = 0; r < 8; r++) {
            unsigned long long al, ah;
            f4_to_u2(*(const float4*)(xr + r * 128 + k4 * 4), al, ah);
#pragma unroll
            for (int c = 0; c < 4; c++) {
                ffma2(acc[r][c], al, bl[c]);
                ffma2(acc[r][c], ah, bh[c]);
            }
        }
    }

    float bb0 = __ldg(bias + tx);
    float bb1 = __ldg(bias + tx + 32);
    float bb2 = __ldg(bias + tx + 64);
    float bb3 = __ldg(bias + tx + 96);
#pragma unroll
    for (int r = 0; r < 8; r++) {
        int row = row0 + ty * 8 + r;
        if (row < N) {
            float* yr = xio + (size_t)row * DD;
            yr[tx]      = fmaxf(u2_sum(acc[r][0]) + bb0, 0.f);
            yr[tx + 32] = fmaxf(u2_sum(acc[r][1]) + bb1, 0.f);
            yr[tx + 64] = fmaxf(u2_sum(acc[r][2]) + bb2, 0.f);
            yr[tx + 96] = fmaxf(u2_sum(acc[r][3]) + bb3, 0.f);
        }
    }
}

// ---------------- attention combine ----------------
__global__ void k_att(const float* __restrict__ y1,
                      const float* __restrict__ y2,
                      const float* __restrict__ y3,
                      const float* __restrict__ att,
                      float* __restrict__ out,
                      int N)
{
    int t = blockIdx.x * blockDim.x + threadIdx.x;
    int n = t >> 5, lane = t & 31;
    if (n >= N) return;
    size_t base = (size_t)n * DD;
    float4 v1 = __ldg((const float4*)(y1 + base) + lane);
    float4 v2 = __ldg((const float4*)(y2 + base) + lane);
    float4 v3 = __ldg((const float4*)(y3 + base) + lane);
    float4 a1 = __ldg((const float4*)att + lane);
    float4 a2 = __ldg((const float4*)att + 32 + lane);
    float4 a3 = __ldg((const float4*)att + 64 + lane);

    float s1 = v1.x * a1.x + v1.y * a1.y + v1.z * a1.z + v1.w * a1.w;
    float s2 = v2.x * a2.x + v2.y * a2.y + v2.z * a2.z + v2.w * a2.w;
    float s3 = v3.x * a3.x + v3.y * a3.y + v3.z * a3.z + v3.w * a3.w;
#pragma unroll
    for (int off = 16; off; off >>= 1) {
        s1 += __shfl_xor_sync(0xFFFFFFFFu, s1, off);
        s2 += __shfl_xor_sync(0xFFFFFFFFu, s2, off);
        s3 += __shfl_xor_sync(0xFFFFFFFFu, s3, off);
    }
    float m = fmaxf(s1, fmaxf(s2, s3));
    float e1 = __expf(s1 - m), e2 = __expf(s2 - m), e3 = __expf(s3 - m);
    float inv = 1.0f / (e1 + e2 + e3);
    float w1 = e1 * inv, w2 = e2 * inv, w3 = e3 * inv;

    float4 o;
    o.x = w1 * v1.x + w2 * v2.x + w3 * v3.x;
    o.y = w1 * v1.y + w2 * v2.y + w3 * v3.y;
    o.z = w1 * v1.z + w2 * v2.z + w3 * v3.z;
    o.w = w1 * v1.w + w2 * v2.w + w3 * v3.w;
    ((float4*)(out + base))[lane] = o;
}

// ---------------- launch ----------------
static inline int cdiv(long long a, int b) { return (int)((a + b - 1) / b); }

extern "C" void kernel_launch(void* const* d_in, const int* in_sizes, int n_in,
                              void* d_out, int out_size)
{
    const float* x_node   = (const float*)d_in[0];
    const float* x1       = (const float*)d_in[1];
    const float* x2       = (const float*)d_in[2];
    const int*   ei1_src  = (const int*)d_in[3];
    const int*   ei1_dst  = (const int*)d_in[4];
    const int*   ei2_src  = (const int*)d_in[5];
    const int*   ei2_dst  = (const int*)d_in[6];
    const int*   ei12_src = (const int*)d_in[7];
    const int*   ei12_dst = (const int*)d_in[8];
    const float* ew1      = (const float*)d_in[9];
    const float* ew2      = (const float*)d_in[10];
    const float* W1       = (const float*)d_in[11];
    const float* b1       = (const float*)d_in[12];
    const float* W2       = (const float*)d_in[13];
    const float* b2       = (const float*)d_in[14];
    const float* W12      = (const float*)d_in[15];
    const float* b12      = (const float*)d_in[16];
    const float* att      = (const float*)d_in[17];
    float* out = (float*)d_out;

    int n0  = in_sizes[0] / DD;
    int n1  = in_sizes[1] / DD;
    int n2  = in_sizes[2] / DD;
    int e1  = in_sizes[3];
    int e2  = in_sizes[5];
    int e12 = in_sizes[7];

    float *net1, *net2, *net2b, *s1, *s2, *s12;
    int *rowptr, *cursor;
    int *p1g, *p2g, *pb1g, *pcg, *pb2g;
    float *p1w, *p2w, *pb2w;
    cudaGetSymbolAddress((void**)&net1,  g_net1);
    cudaGetSymbolAddress((void**)&net2,  g_net2);
    cudaGetSymbolAddress((void**)&net2b, g_net2b);
    cudaGetSymbolAddress((void**)&s1,  g_s1);
    cudaGetSymbolAddress((void**)&s2,  g_s2);
    cudaGetSymbolAddress((void**)&s12, g_s12);
    cudaGetSymbolAddress((void**)&rowptr, g_rowptr);
    cudaGetSymbolAddress((void**)&cursor, g_cursor);
    cudaGetSymbolAddress((void**)&p1g,  g_p1g);
    cudaGetSymbolAddress((void**)&p1w,  g_p1w);
    cudaGetSymbolAddress((void**)&p2g,  g_p2g);
    cudaGetSymbolAddress((void**)&p2w,  g_p2w);
    cudaGetSymbolAddress((void**)&pb1g, g_pb1g);
    cudaGetSymbolAddress((void**)&pcg,  g_pcg);
    cudaGetSymbolAddress((void**)&pb2g, g_pb2g);
    cudaGetSymbolAddress((void**)&pb2w, g_pb2w);

    cudaFuncSetAttribute(k_gemm_relu, cudaFuncAttributeMaxDynamicSharedMemorySize, GEMM_SMEM);

    // zero only histograms (1.2MB)
    cudaMemsetAsync(cursor, 0, (size_t)RPTOT * sizeof(int), 0);

    const int BT = 256;

    // --- histograms ---
    k_hist<<<cdiv(e1, BT), BT>>>(ei1_dst,  cursor + RP1,  e1);
    k_hist<<<cdiv(e2, BT), BT>>>(ei2_dst,  cursor + RP2,  e2);
    k_hist<<<cdiv(e1, BT), BT>>>(ei1_src,  cursor + RPB1, e1);
    k_hist<<<cdiv(e12, BT), BT>>>(ei12_dst, cursor + RPC,  e12);
    k_hist<<<cdiv(e2, BT), BT>>>(ei2_src,  cursor + RPB2, e2);

    // --- fused scans (5 blocks, one per CSR) ---
    Seg5 segs;
    segs.off[0] = RP1;  segs.n[0] = n1;
    segs.off[1] = RP2;  segs.n[1] = n2;
    segs.off[2] = RPB1; segs.n[2] = n0;
    segs.off[3] = RPC;  segs.n[3] = n2;
    segs.off[4] = RPB2; segs.n[4] = n0;
    k_scan5<<<5, 1024>>>(rowptr, cursor, segs);

    // --- binning ---
    k_bin<<<cdiv(e1, BT), BT>>>(ei1_dst,  ei1_src,  ew1, cursor + RP1,  p1g,  p1w,  e1);
    k_bin<<<cdiv(e2, BT), BT>>>(ei2_dst,  ei2_src,  ew2, cursor + RP2,  p2g,  p2w,  e2);
    k_bin<<<cdiv(e1, BT), BT>>>(ei1_src,  ei1_dst,  (const float*)0, cursor + RPB1, pb1g, (float*)0, e1);
    k_bin<<<cdiv(e12, BT), BT>>>(ei12_dst, ei12_src, (const float*)0, cursor + RPC,  pcg,  (float*)0, e12);
    k_bin<<<cdiv(e2, BT), BT>>>(ei2_src,  ei2_dst,  ew2, cursor + RPB2, pb2g, pb2w, e2);

    // --- gathers (atomic-free) ---
    k_gather_msg<<<cdiv((long long)n1 * 32, BT), BT>>>(x_node, p1g, p1w, rowptr + RP1, x1, net1, n1);
    k_gather_msg<<<cdiv((long long)n2 * 32, BT), BT>>>(x_node, p2g, p2w, rowptr + RP2, x2, net2, n2);
    k_gather_s<<<cdiv((long long)n0 * 32, BT), BT>>>(net1, pb1g, rowptr + RPB1, s1, n0);
    k_gather_msg<<<cdiv((long long)n2 * 32, BT), BT>>>(net1, pcg, (const float*)0, rowptr + RPC, x2, net2b, n2);
    k_gather_dual<<<cdiv((long long)n0 * 32, BT), BT>>>(net2, net2b, pb2g, pb2w, rowptr + RPB2, s2, s12, n0);

    // --- GEMM + ReLU (in place) ---
    dim3 gblk(32, 8);
    k_gemm_relu<<<cdiv(n0, 64), gblk, GEMM_SMEM>>>(s1,  W1,  b1,  n0);
    k_gemm_relu<<<cdiv(n0, 64), gblk, GEMM_SMEM>>>(s2,  W2,  b2,  n0);
    k_gemm_relu<<<cdiv(n0, 64), gblk, GEMM_SMEM>>>(s12, W12, b12, n0);

    // --- attention combine ---
    k_att<<<cdiv((long long)n0 * 32, BT), BT>>>(s1, s2, s12, att, out, n0);
}

// round 9
// speedup vs baseline: 1.3543x; 1.2334x over previous
#include <cuda_runtime.h>
#include <cuda_fp16.h>
#include <math.h>

#define DD 128
#define N0CAP 100000
#define N1CAP 50000
#define N2CAP 50000
#define E1CAP 1600000
#define E2CAP 1600000
#define E12CAP 800000

// ---------------- scratch ----------------
__device__ __half g_net1h [N1CAP * DD];
__device__ __half g_net2h [N2CAP * DD];
__device__ __half g_net2bh[N2CAP * DD];
__device__ float  g_s1 [N0CAP * DD];
__device__ float  g_s2 [N0CAP * DD];
__device__ float  g_s12[N0CAP * DD];

#define RP1   0
#define RP2   (RP1 + N1CAP + 1)
#define RPB1  (RP2 + N2CAP + 1)
#define RPC   (RPB1 + N0CAP + 1)
#define RPB2  (RPC + N2CAP + 1)
#define RPTOT (RPB2 + N0CAP + 1)
__device__ int g_rowptr[RPTOT];
__device__ int g_cursor[RPTOT];   // doubles as histogram

__device__ int2 g_p1gw [E1CAP];   // (gather idx, weight bits)
__device__ int2 g_p2gw [E2CAP];
__device__ int2 g_pb2gw[E2CAP];
__device__ int  g_pb1g [E1CAP];
__device__ int  g_pcg  [E12CAP];

// ---------------- histogram ----------------
__global__ void k_hist(const int* __restrict__ idx, int* __restrict__ hist, int E)
{
    int e = blockIdx.x * blockDim.x + threadIdx.x;
    if (e < E) atomicAdd(hist + __ldg(idx + e), 1);
}

// ---------------- fused exclusive scan over 5 segments ----------------
struct Seg5 { int off[5]; int n[5]; };
__global__ void k_scan5(int* __restrict__ rowptr_base, int* __restrict__ cur_base, Seg5 segs)
{
    __shared__ int wsum[32];
    int off = segs.off[blockIdx.x];
    int N   = segs.n[blockIdx.x];
    int* hist = cur_base + off;
    int* rp   = rowptr_base + off;

    int tid = threadIdx.x;                 // blockDim = 1024
    int per = (N + 1023) >> 10;
    int lo = tid * per; if (lo > N) lo = N;
    int hi = lo + per;  if (hi > N) hi = N;

    int sum = 0;
    for (int i = lo; i < hi; i++) sum += hist[i];

    int lane = tid & 31, wid = tid >> 5;
    int v = sum;
#pragma unroll
    for (int o = 1; o < 32; o <<= 1) {
        int t = __shfl_up_sync(0xffffffffu, v, o);
        if (lane >= o) v += t;
    }
    if (lane == 31) wsum[wid] = v;
    __syncthreads();
    if (wid == 0) {
        int s = wsum[lane];
#pragma unroll
        for (int o = 1; o < 32; o <<= 1) {
            int t = __shfl_up_sync(0xffffffffu, s, o);
            if (lane >= o) s += t;
        }
        wsum[lane] = s;
    }
    __syncthreads();
    int excl = (v - sum) + (wid ? wsum[wid - 1] : 0);

    int run = excl;
    for (int i = lo; i < hi; i++) {
        int c = hist[i];
        rp[i] = run;
        hist[i] = run;
        run += c;
    }
    if (tid == 1023) rp[N] = excl + sum;
}

// ---------------- binning: weighted (packed int2) ----------------
__global__ void k_bin_w(const int*   __restrict__ sc_idx,
                        const int*   __restrict__ g_idx,
                        const float* __restrict__ ew,
                        int*  __restrict__ cursor,
                        int2* __restrict__ pgw,
                        int E)
{
    int e = blockIdx.x * blockDim.x + threadIdx.x;
    if (e >= E) return;
    int b = __ldg(sc_idx + e);
    int p = atomicAdd(cursor + b, 1);
    pgw[p] = make_int2(__ldg(g_idx + e), __float_as_int(__ldg(ew + e)));
}

// ---------------- binning: unweighted ----------------
__global__ void k_bin_u(const int* __restrict__ sc_idx,
                        const int* __restrict__ g_idx,
                        int* __restrict__ cursor,
                        int* __restrict__ pg,
                        int E)
{
    int e = blockIdx.x * blockDim.x + threadIdx.x;
    if (e >= E) return;
    int b = __ldg(sc_idx + e);
    int p = atomicAdd(cursor + b, 1);
    pg[p] = __ldg(g_idx + e);
}

// ======== gather A: fp32 src, weighted(packed), out = half((mean + xb)*0.5) ========
__global__ void k_gather_msg_h(const float* __restrict__ feat,
                               const int2*  __restrict__ pgw,
                               const int*   __restrict__ rp,
                               const float* __restrict__ xb,
                               __half* __restrict__ outh,
                               int N)
{
    int t = blockIdx.x * blockDim.x + threadIdx.x;
    int n = t >> 5, lane = t & 31;
    if (n >= N) return;
    int start = __ldg(rp + n), end = __ldg(rp + n + 1);

    float4 acc = make_float4(0.f, 0.f, 0.f, 0.f);
    int j = start;
    for (; j + 4 <= end; j += 4) {
        int2 e0 = __ldg(pgw + j),     e1 = __ldg(pgw + j + 1);
        int2 e2 = __ldg(pgw + j + 2), e3 = __ldg(pgw + j + 3);
        float4 v0 = __ldg((const float4*)(feat + (size_t)e0.x * DD) + lane);
        float4 v1 = __ldg((const float4*)(feat + (size_t)e1.x * DD) + lane);
        float4 v2 = __ldg((const float4*)(feat + (size_t)e2.x * DD) + lane);
        float4 v3 = __ldg((const float4*)(feat + (size_t)e3.x * DD) + lane);
        float w0 = __int_as_float(e0.y), w1 = __int_as_float(e1.y);
        float w2 = __int_as_float(e2.y), w3 = __int_as_float(e3.y);
        acc.x += v0.x * w0 + v1.x * w1 + v2.x * w2 + v3.x * w3;
        acc.y += v0.y * w0 + v1.y * w1 + v2.y * w2 + v3.y * w3;
        acc.z += v0.z * w0 + v1.z * w1 + v2.z * w2 + v3.z * w3;
        acc.w += v0.w * w0 + v1.w * w1 + v2.w * w2 + v3.w * w3;
    }
    for (; j < end; j++) {
        int2 e = __ldg(pgw + j);
        float w = __int_as_float(e.y);
        float4 v = __ldg((const float4*)(feat + (size_t)e.x * DD) + lane);
        acc.x += v.x * w; acc.y += v.y * w; acc.z += v.z * w; acc.w += v.w * w;
    }
    int deg = end - start;
    float inv = 1.0f / (deg > 1 ? (float)deg : 1.0f);
    float4 x = __ldg((const float4*)(xb + (size_t)n * DD) + lane);
    float4 r;
    r.x = (acc.x * inv + x.x) * 0.5f;
    r.y = (acc.y * inv + x.y) * 0.5f;
    r.z = (acc.z * inv + x.z) * 0.5f;
    r.w = (acc.w * inv + x.w) * 0.5f;
    __half2 h0 = __floats2half2_rn(r.x, r.y);
    __half2 h1 = __floats2half2_rn(r.z, r.w);
    uint2 o = make_uint2(*(unsigned*)&h0, *(unsigned*)&h1);
    ((uint2*)outh)[(size_t)n * 32 + lane] = o;
}

// ======== gather B: fp16 src, unweighted, out fp32 mean ========
__global__ void k_gather_s_h(const __half* __restrict__ feath,
                             const int*    __restrict__ pg,
                             const int*    __restrict__ rp,
                             float* __restrict__ out,
                             int N)
{
    int t = blockIdx.x * blockDim.x + threadIdx.x;
    int n = t >> 5, lane = t & 31;
    if (n >= N) return;
    int start = __ldg(rp + n), end = __ldg(rp + n + 1);
    const uint2* fb = (const uint2*)feath;   // 32 uint2 per row

    float4 acc = make_float4(0.f, 0.f, 0.f, 0.f);
    int j = start;
    for (; j + 4 <= end; j += 4) {
        int g0 = __ldg(pg + j), g1 = __ldg(pg + j + 1);
        int g2 = __ldg(pg + j + 2), g3 = __ldg(pg + j + 3);
        uint2 u0 = __ldg(fb + (size_t)g0 * 32 + lane);
        uint2 u1 = __ldg(fb + (size_t)g1 * 32 + lane);
        uint2 u2 = __ldg(fb + (size_t)g2 * 32 + lane);
        uint2 u3 = __ldg(fb + (size_t)g3 * 32 + lane);
#pragma unroll
        for (int q = 0; q < 4; q++) {
            uint2 u = (q == 0) ? u0 : (q == 1) ? u1 : (q == 2) ? u2 : u3;
            float2 f0 = __half22float2(*(__half2*)&u.x);
            float2 f1 = __half22float2(*(__half2*)&u.y);
            acc.x += f0.x; acc.y += f0.y; acc.z += f1.x; acc.w += f1.y;
        }
    }
    for (; j < end; j++) {
        int g = __ldg(pg + j);
        uint2 u = __ldg(fb + (size_t)g * 32 + lane);
        float2 f0 = __half22float2(*(__half2*)&u.x);
        float2 f1 = __half22float2(*(__half2*)&u.y);
        acc.x += f0.x; acc.y += f0.y; acc.z += f1.x; acc.w += f1.y;
    }
    int deg = end - start;
    float inv = 1.0f / (deg > 1 ? (float)deg : 1.0f);
    float4 o = make_float4(acc.x * inv, acc.y * inv, acc.z * inv, acc.w * inv);
    ((float4*)(out + (size_t)n * DD))[lane] = o;
}

// ======== gather C: fp16 src, unweighted, out = half((mean + xb)*0.5) ========
__global__ void k_gather_msg_hh(const __half* __restrict__ feath,
                                const int*    __restrict__ pg,
                                const int*    __restrict__ rp,
                                const float*  __restrict__ xb,
                                __half* __restrict__ outh,
                                int N)
{
    int t = blockIdx.x * blockDim.x + threadIdx.x;
    int n = t >> 5, lane = t & 31;
    if (n >= N) return;
    int start = __ldg(rp + n), end = __ldg(rp + n + 1);
    const uint2* fb = (const uint2*)feath;

    float4 acc = make_float4(0.f, 0.f, 0.f, 0.f);
    int j = start;
    for (; j + 4 <= end; j += 4) {
        int g0 = __ldg(pg + j), g1 = __ldg(pg + j + 1);
        int g2 = __ldg(pg + j + 2), g3 = __ldg(pg + j + 3);
        uint2 u0 = __ldg(fb + (size_t)g0 * 32 + lane);
        uint2 u1 = __ldg(fb + (size_t)g1 * 32 + lane);
        uint2 u2 = __ldg(fb + (size_t)g2 * 32 + lane);
        uint2 u3 = __ldg(fb + (size_t)g3 * 32 + lane);
#pragma unroll
        for (int q = 0; q < 4; q++) {
            uint2 u = (q == 0) ? u0 : (q == 1) ? u1 : (q == 2) ? u2 : u3;
            float2 f0 = __half22float2(*(__half2*)&u.x);
            float2 f1 = __half22float2(*(__half2*)&u.y);
            acc.x += f0.x; acc.y += f0.y; acc.z += f1.x; acc.w += f1.y;
        }
    }
    for (; j < end; j++) {
        int g = __ldg(pg + j);
        uint2 u = __ldg(fb + (size_t)g * 32 + lane);
        float2 f0 = __half22float2(*(__half2*)&u.x);
        float2 f1 = __half22float2(*(__half2*)&u.y);
        acc.x += f0.x; acc.y += f0.y; acc.z += f1.x; acc.w += f1.y;
    }
    int deg = end - start;
    float inv = 1.0f / (deg > 1 ? (float)deg : 1.0f);
    float4 x = __ldg((const float4*)(xb + (size_t)n * DD) + lane);
    float4 r;
    r.x = (acc.x * inv + x.x) * 0.5f;
    r.y = (acc.y * inv + x.y) * 0.5f;
    r.z = (acc.z * inv + x.z) * 0.5f;
    r.w = (acc.w * inv + x.w) * 0.5f;
    __half2 h0 = __floats2half2_rn(r.x, r.y);
    __half2 h1 = __floats2half2_rn(r.z, r.w);
    uint2 o = make_uint2(*(unsigned*)&h0, *(unsigned*)&h1);
    ((uint2*)outh)[(size_t)n * 32 + lane] = o;
}

// ======== dual gather: fp16 srcs, packed weight (b only), fp32 outs ========
__global__ void k_gather_dual_h(const __half* __restrict__ feat_a,
                                const __half* __restrict__ feat_b,
                                const int2*   __restrict__ pgw,
                                const int*    __restrict__ rp,
                                float* __restrict__ out_a,
                                float* __restrict__ out_b,
                                int N)
{
    int t = blockIdx.x * blockDim.x + threadIdx.x;
    int n = t >> 5, lane = t & 31;
    if (n >= N) return;
    int start = __ldg(rp + n), end = __ldg(rp + n + 1);
    const uint2* fa = (const uint2*)feat_a;
    const uint2* fbp = (const uint2*)feat_b;

    float4 aa = make_float4(0.f, 0.f, 0.f, 0.f);
    float4 ab = make_float4(0.f, 0.f, 0.f, 0.f);
    int j = start;
    for (; j + 2 <= end; j += 2) {
        int2 e0 = __ldg(pgw + j), e1 = __ldg(pgw + j + 1);
        uint2 a0 = __ldg(fa  + (size_t)e0.x * 32 + lane);
        uint2 b0 = __ldg(fbp + (size_t)e0.x * 32 + lane);
        uint2 a1 = __ldg(fa  + (size_t)e1.x * 32 + lane);
        uint2 b1 = __ldg(fbp + (size_t)e1.x * 32 + lane);
        float w0 = __int_as_float(e0.y), w1 = __int_as_float(e1.y);
        {
            float2 f0 = __half22float2(*(__half2*)&a0.x);
            float2 f1 = __half22float2(*(__half2*)&a0.y);
            float2 g0 = __half22float2(*(__half2*)&a1.x);
            float2 g1 = __half22float2(*(__half2*)&a1.y);
            aa.x += f0.x + g0.x; aa.y += f0.y + g0.y;
            aa.z += f1.x + g1.x; aa.w += f1.y + g1.y;
        }
        {
            float2 f0 = __half22float2(*(__half2*)&b0.x);
            float2 f1 = __half22float2(*(__half2*)&b0.y);
            float2 g0 = __half22float2(*(__half2*)&b1.x);
            float2 g1 = __half22float2(*(__half2*)&b1.y);
            ab.x += f0.x * w0 + g0.x * w1; ab.y += f0.y * w0 + g0.y * w1;
            ab.z += f1.x * w0 + g1.x * w1; ab.w += f1.y * w0 + g1.y * w1;
        }
    }
    for (; j < end; j++) {
        int2 e = __ldg(pgw + j);
        float w = __int_as_float(e.y);
        uint2 a = __ldg(fa  + (size_t)e.x * 32 + lane);
        uint2 b = __ldg(fbp + (size_t)e.x * 32 + lane);
        float2 f0 = __half22float2(*(__half2*)&a.x);
        float2 f1 = __half22float2(*(__half2*)&a.y);
        aa.x += f0.x; aa.y += f0.y; aa.z += f1.x; aa.w += f1.y;
        float2 h0 = __half22float2(*(__half2*)&b.x);
        float2 h1 = __half22float2(*(__half2*)&b.y);
        ab.x += h0.x * w; ab.y += h0.y * w; ab.z += h1.x * w; ab.w += h1.y * w;
    }
    int deg = end - start;
    float inv = 1.0f / (deg > 1 ? (float)deg : 1.0f);
    float4 oa = make_float4(aa.x * inv, aa.y * inv, aa.z * inv, aa.w * inv);
    float4 ob = make_float4(ab.x * inv, ab.y * inv, ab.z * inv, ab.w * inv);
    ((float4*)(out_a + (size_t)n * DD))[lane] = oa;
    ((float4*)(out_b + (size_t)n * DD))[lane] = ob;
}

// ---------------- GEMM (R4 version, unchanged): y = relu(x @ W^T + b), in place ----------------
#define GEMM_SMEM (64 * 128 * 4 + 129 * 128 * 4)

__device__ __forceinline__ void ffma2(unsigned long long& d, unsigned long long a,
                                      unsigned long long b) {
    asm("fma.rn.f32x2 %0, %1, %2, %0;" : "+l"(d) : "l"(a), "l"(b));
}
__device__ __forceinline__ unsigned long long pack2(float lo, float hi) {
    unsigned long long r;
    asm("mov.b64 %0, {%1, %2};" : "=l"(r) : "f"(lo), "f"(hi));
    return r;
}
__device__ __forceinline__ void unpack2(unsigned long long v, float& lo, float& hi) {
    asm("mov.b64 {%0, %1}, %2;" : "=f"(lo), "=f"(hi) : "l"(v));
}

__global__ void k_gemm_relu(float* __restrict__ xio,
                            const float* __restrict__ W,
                            const float* __restrict__ bias,
                            int N)
{
    extern __shared__ float sm[];
    float* xs = sm;              // [64][128]
    float* ws = sm + 64 * 128;   // [128][129] transposed W
    int tx = threadIdx.x, ty = threadIdx.y;
    int tid = ty * 32 + tx;
    int row0 = blockIdx.x * 64;

    for (int idx = tid; idx < 128 * 128; idx += 256) {
        int i = idx >> 7, k = idx & 127;
        ws[k * 129 + i] = __ldg(W + idx);
    }
    for (int idx = tid; idx < 64 * 32; idx += 256) {
        int r = idx >> 5;
        int row = row0 + r;
        float4 v = make_float4(0.f, 0.f, 0.f, 0.f);
        if (row < N) v = ((const float4*)(xio + (size_t)row * DD))[idx & 31];
        ((float4*)xs)[idx] = v;
    }
    __syncthreads();

    unsigned long long accA[8], accB[8];
#pragma unroll
    for (int r = 0; r < 8; r++) { accA[r] = 0ull; accB[r] = 0ull; }

#pragma unroll 4
    for (int k = 0; k < 128; k++) {
        float b0 = ws[k * 129 + tx];
        float b1 = ws[k * 129 + tx + 32];
        float b2 = ws[k * 129 + tx + 64];
        float b3 = ws[k * 129 + tx + 96];
        unsigned long long bA = pack2(b0, b1);
        unsigned long long bB = pack2(b2, b3);
#pragma unroll
        for (int r = 0; r < 8; r++) {
            float a = xs[(ty * 8 + r) * 128 + k];
            unsigned long long aa = pack2(a, a);
            ffma2(accA[r], aa, bA);
            ffma2(accB[r], aa, bB);
        }
    }

    float bb0 = __ldg(bias + tx);
    float bb1 = __ldg(bias + tx + 32);
    float bb2 = __ldg(bias + tx + 64);
    float bb3 = __ldg(bias + tx + 96);
#pragma unroll
    for (int r = 0; r < 8; r++) {
        int row = row0 + ty * 8 + r;
        if (row < N) {
            float a0, a1, a2, a3;
            unpack2(accA[r], a0, a1);
            unpack2(accB[r], a2, a3);
            float* yr = xio + (size_t)row * DD;
            yr[tx]      = fmaxf(a0 + bb0, 0.f);
            yr[tx + 32] = fmaxf(a1 + bb1, 0.f);
            yr[tx + 64] = fmaxf(a2 + bb2, 0.f);
            yr[tx + 96] = fmaxf(a3 + bb3, 0.f);
        }
    }
}

// ---------------- attention combine ----------------
__global__ void k_att(const float* __restrict__ y1,
                      const float* __restrict__ y2,
                      const float* __restrict__ y3,
                      const float* __restrict__ att,
                      float* __restrict__ out,
                      int N)
{
    int t = blockIdx.x * blockDim.x + threadIdx.x;
    int n = t >> 5, lane = t & 31;
    if (n >= N) return;
    size_t base = (size_t)n * DD;
    float4 v1 = __ldg((const float4*)(y1 + base) + lane);
    float4 v2 = __ldg((const float4*)(y2 + base) + lane);
    float4 v3 = __ldg((const float4*)(y3 + base) + lane);
    float4 a1 = __ldg((const float4*)att + lane);
    float4 a2 = __ldg((const float4*)att + 32 + lane);
    float4 a3 = __ldg((const float4*)att + 64 + lane);

    float s1 = v1.x * a1.x + v1.y * a1.y + v1.z * a1.z + v1.w * a1.w;
    float s2 = v2.x * a2.x + v2.y * a2.y + v2.z * a2.z + v2.w * a2.w;
    float s3 = v3.x * a3.x + v3.y * a3.y + v3.z * a3.z + v3.w * a3.w;
#pragma unroll
    for (int off = 16; off; off >>= 1) {
        s1 += __shfl_xor_sync(0xFFFFFFFFu, s1, off);
        s2 += __shfl_xor_sync(0xFFFFFFFFu, s2, off);
        s3 += __shfl_xor_sync(0xFFFFFFFFu, s3, off);
    }
    float m = fmaxf(s1, fmaxf(s2, s3));
    float e1 = __expf(s1 - m), e2 = __expf(s2 - m), e3 = __expf(s3 - m);
    float inv = 1.0f / (e1 + e2 + e3);
    float w1 = e1 * inv, w2 = e2 * inv, w3 = e3 * inv;

    float4 o;
    o.x = w1 * v1.x + w2 * v2.x + w3 * v3.x;
    o.y = w1 * v1.y + w2 * v2.y + w3 * v3.y;
    o.z = w1 * v1.z + w2 * v2.z + w3 * v3.z;
    o.w = w1 * v1.w + w2 * v2.w + w3 * v3.w;
    ((float4*)(out + base))[lane] = o;
}

// ---------------- launch ----------------
static inline int cdiv(long long a, int b) { return (int)((a + b - 1) / b); }

extern "C" void kernel_launch(void* const* d_in, const int* in_sizes, int n_in,
                              void* d_out, int out_size)
{
    const float* x_node   = (const float*)d_in[0];
    const float* x1       = (const float*)d_in[1];
    const float* x2       = (const float*)d_in[2];
    const int*   ei1_src  = (const int*)d_in[3];
    const int*   ei1_dst  = (const int*)d_in[4];
    const int*   ei2_src  = (const int*)d_in[5];
    const int*   ei2_dst  = (const int*)d_in[6];
    const int*   ei12_src = (const int*)d_in[7];
    const int*   ei12_dst = (const int*)d_in[8];
    const float* ew1      = (const float*)d_in[9];
    const float* ew2      = (const float*)d_in[10];
    const float* W1       = (const float*)d_in[11];
    const float* b1       = (const float*)d_in[12];
    const float* W2       = (const float*)d_in[13];
    const float* b2       = (const float*)d_in[14];
    const float* W12      = (const float*)d_in[15];
    const float* b12      = (const float*)d_in[16];
    const float* att      = (const float*)d_in[17];
    float* out = (float*)d_out;

    int n0  = in_sizes[0] / DD;
    int n1  = in_sizes[1] / DD;
    int n2  = in_sizes[2] / DD;
    int e1  = in_sizes[3];
    int e2  = in_sizes[5];
    int e12 = in_sizes[7];

    __half *net1h, *net2h, *net2bh;
    float *s1, *s2, *s12;
    int *rowptr, *cursor, *pb1g, *pcg;
    int2 *p1gw, *p2gw, *pb2gw;
    cudaGetSymbolAddress((void**)&net1h,  g_net1h);
    cudaGetSymbolAddress((void**)&net2h,  g_net2h);
    cudaGetSymbolAddress((void**)&net2bh, g_net2bh);
    cudaGetSymbolAddress((void**)&s1,  g_s1);
    cudaGetSymbolAddress((void**)&s2,  g_s2);
    cudaGetSymbolAddress((void**)&s12, g_s12);
    cudaGetSymbolAddress((void**)&rowptr, g_rowptr);
    cudaGetSymbolAddress((void**)&cursor, g_cursor);
    cudaGetSymbolAddress((void**)&p1gw,  g_p1gw);
    cudaGetSymbolAddress((void**)&p2gw,  g_p2gw);
    cudaGetSymbolAddress((void**)&pb2gw, g_pb2gw);
    cudaGetSymbolAddress((void**)&pb1g,  g_pb1g);
    cudaGetSymbolAddress((void**)&pcg,   g_pcg);

    cudaFuncSetAttribute(k_gemm_relu, cudaFuncAttributeMaxDynamicSharedMemorySize, GEMM_SMEM);

    cudaMemsetAsync(cursor, 0, (size_t)RPTOT * sizeof(int), 0);

    const int BT = 256;

    // --- histograms ---
    k_hist<<<cdiv(e1, BT), BT>>>(ei1_dst,   cursor + RP1,  e1);
    k_hist<<<cdiv(e2, BT), BT>>>(ei2_dst,   cursor + RP2,  e2);
    k_hist<<<cdiv(e1, BT), BT>>>(ei1_src,   cursor + RPB1, e1);
    k_hist<<<cdiv(e12, BT), BT>>>(ei12_dst, cursor + RPC,  e12);
    k_hist<<<cdiv(e2, BT), BT>>>(ei2_src,   cursor + RPB2, e2);

    // --- fused scans ---
    Seg5 segs;
    segs.off[0] = RP1;  segs.n[0] = n1;
    segs.off[1] = RP2;  segs.n[1] = n2;
    segs.off[2] = RPB1; segs.n[2] = n0;
    segs.off[3] = RPC;  segs.n[3] = n2;
    segs.off[4] = RPB2; segs.n[4] = n0;
    k_scan5<<<5, 1024>>>(rowptr, cursor, segs);

    // --- binning ---
    k_bin_w<<<cdiv(e1, BT), BT>>>(ei1_dst,  ei1_src,  ew1, cursor + RP1,  p1gw,  e1);
    k_bin_w<<<cdiv(e2, BT), BT>>>(ei2_dst,  ei2_src,  ew2, cursor + RP2,  p2gw,  e2);
    k_bin_u<<<cdiv(e1, BT), BT>>>(ei1_src,  ei1_dst,  cursor + RPB1, pb1g, e1);
    k_bin_u<<<cdiv(e12, BT), BT>>>(ei12_dst, ei12_src, cursor + RPC,  pcg,  e12);
    k_bin_w<<<cdiv(e2, BT), BT>>>(ei2_src,  ei2_dst,  ew2, cursor + RPB2, pb2gw, e2);

    // --- gathers ---
    // net1h = half((mean(x_node[src]*ew1 by dst) + x1)*0.5)
    k_gather_msg_h<<<cdiv((long long)n1 * 32, BT), BT>>>(x_node, p1gw, rowptr + RP1, x1, net1h, n1);
    // net2h likewise
    k_gather_msg_h<<<cdiv((long long)n2 * 32, BT), BT>>>(x_node, p2gw, rowptr + RP2, x2, net2h, n2);
    // s1 = mean(net1h[dst] by src)  (fp32 out)
    k_gather_s_h<<<cdiv((long long)n0 * 32, BT), BT>>>(net1h, pb1g, rowptr + RPB1, s1, n0);
    // net2bh = half((mean(net1h[ei12_src] by ei12_dst) + x2)*0.5)
    k_gather_msg_hh<<<cdiv((long long)n2 * 32, BT), BT>>>(net1h, pcg, rowptr + RPC, x2, net2bh, n2);
    // s2 = mean(net2h); s12 = mean(net2bh*ew2)  (fp32 outs)
    k_gather_dual_h<<<cdiv((long long)n0 * 32, BT), BT>>>(net2h, net2bh, pb2gw, rowptr + RPB2, s2, s12, n0);

    // --- GEMM + ReLU (in place) ---
    dim3 gblk(32, 8);
    k_gemm_relu<<<cdiv(n0, 64), gblk, GEMM_SMEM>>>(s1,  W1,  b1,  n0);
    k_gemm_relu<<<cdiv(n0, 64), gblk, GEMM_SMEM>>>(s2,  W2,  b2,  n0);
    k_gemm_relu<<<cdiv(n0, 64), gblk, GEMM_SMEM>>>(s12, W12, b12, n0);

    // --- attention combine ---
    k_att<<<cdiv((long long)n0 * 32, BT), BT>>>(s1, s2, s12, att, out, n0);
}

// round 10
// speedup vs baseline: 1.3940x; 1.0293x over previous
#include <cuda_runtime.h>
#include <cuda_fp16.h>
#include <math.h>

#define DD 128
#define N0CAP 100000
#define N1CAP 50000
#define N2CAP 50000
#define E1CAP 1600000
#define E2CAP 1600000
#define E12CAP 800000

// ---------------- scratch ----------------
__device__ __half g_xnodeh[N0CAP * DD];
__device__ __half g_net1h [N1CAP * DD];
__device__ __half g_net2h [N2CAP * DD];
__device__ __half g_net2bh[N2CAP * DD];
__device__ float  g_s1 [N0CAP * DD];
__device__ float  g_s2 [N0CAP * DD];
__device__ float  g_s12[N0CAP * DD];

#define RP1   0
#define RP2   (RP1 + N1CAP + 1)
#define RPB1  (RP2 + N2CAP + 1)
#define RPC   (RPB1 + N0CAP + 1)
#define RPB2  (RPC + N2CAP + 1)
#define RPTOT (RPB2 + N0CAP + 1)
__device__ int g_rowptr[RPTOT];
__device__ int g_cursor[RPTOT];   // doubles as histogram

__device__ int2 g_p1gw [E1CAP];   // (gather idx, weight bits)
__device__ int2 g_p2gw [E2CAP];
__device__ int2 g_pb2gw[E2CAP];
__device__ int  g_pb1g [E1CAP];
__device__ int  g_pcg  [E12CAP];

// ---------------- fp32 -> fp16 conversion (streaming) ----------------
__global__ void k_f2h(const float* __restrict__ src, __half* __restrict__ dst, int n4)
{
    int t = blockIdx.x * blockDim.x + threadIdx.x;
    if (t >= n4) return;
    float4 v = __ldg((const float4*)src + t);
    __half2 h0 = __floats2half2_rn(v.x, v.y);
    __half2 h1 = __floats2half2_rn(v.z, v.w);
    ((uint2*)dst)[t] = make_uint2(*(unsigned*)&h0, *(unsigned*)&h1);
}

// ---------------- histogram ----------------
__global__ void k_hist(const int* __restrict__ idx, int* __restrict__ hist, int E)
{
    int e = blockIdx.x * blockDim.x + threadIdx.x;
    if (e < E) atomicAdd(hist + __ldg(idx + e), 1);
}

// ---------------- fused exclusive scan over 5 segments ----------------
struct Seg5 { int off[5]; int n[5]; };
__global__ void k_scan5(int* __restrict__ rowptr_base, int* __restrict__ cur_base, Seg5 segs)
{
    __shared__ int wsum[32];
    int off = segs.off[blockIdx.x];
    int N   = segs.n[blockIdx.x];
    int* hist = cur_base + off;
    int* rp   = rowptr_base + off;

    int tid = threadIdx.x;                 // blockDim = 1024
    int per = (N + 1023) >> 10;
    int lo = tid * per; if (lo > N) lo = N;
    int hi = lo + per;  if (hi > N) hi = N;

    int sum = 0;
    for (int i = lo; i < hi; i++) sum += hist[i];

    int lane = tid & 31, wid = tid >> 5;
    int v = sum;
#pragma unroll
    for (int o = 1; o < 32; o <<= 1) {
        int t = __shfl_up_sync(0xffffffffu, v, o);
        if (lane >= o) v += t;
    }
    if (lane == 31) wsum[wid] = v;
    __syncthreads();
    if (wid == 0) {
        int s = wsum[lane];
#pragma unroll
        for (int o = 1; o < 32; o <<= 1) {
            int t = __shfl_up_sync(0xffffffffu, s, o);
            if (lane >= o) s += t;
        }
        wsum[lane] = s;
    }
    __syncthreads();
    int excl = (v - sum) + (wid ? wsum[wid - 1] : 0);

    int run = excl;
    for (int i = lo; i < hi; i++) {
        int c = hist[i];
        rp[i] = run;
        hist[i] = run;
        run += c;
    }
    if (tid == 1023) rp[N] = excl + sum;
}

// ---------------- binning: weighted (packed int2) ----------------
__global__ void k_bin_w(const int*   __restrict__ sc_idx,
                        const int*   __restrict__ g_idx,
                        const float* __restrict__ ew,
                        int*  __restrict__ cursor,
                        int2* __restrict__ pgw,
                        int E)
{
    int e = blockIdx.x * blockDim.x + threadIdx.x;
    if (e >= E) return;
    int b = __ldg(sc_idx + e);
    int p = atomicAdd(cursor + b, 1);
    pgw[p] = make_int2(__ldg(g_idx + e), __float_as_int(__ldg(ew + e)));
}

// ---------------- binning: unweighted ----------------
__global__ void k_bin_u(const int* __restrict__ sc_idx,
                        const int* __restrict__ g_idx,
                        int* __restrict__ cursor,
                        int* __restrict__ pg,
                        int E)
{
    int e = blockIdx.x * blockDim.x + threadIdx.x;
    if (e >= E) return;
    int b = __ldg(sc_idx + e);
    int p = atomicAdd(cursor + b, 1);
    pg[p] = __ldg(g_idx + e);
}

// ======== gather A: fp16 src, weighted(packed), out = half((mean + xb)*0.5) ========
__global__ void k_gather_msg_h16(const __half* __restrict__ feath,
                                 const int2*   __restrict__ pgw,
                                 const int*    __restrict__ rp,
                                 const float*  __restrict__ xb,
                                 __half* __restrict__ outh,
                                 int N)
{
    int t = blockIdx.x * blockDim.x + threadIdx.x;
    int n = t >> 5, lane = t & 31;
    if (n >= N) return;
    int start = __ldg(rp + n), end = __ldg(rp + n + 1);
    const uint2* fb = (const uint2*)feath;   // 32 uint2 per row

    float4 acc = make_float4(0.f, 0.f, 0.f, 0.f);
    int j = start;
    for (; j + 4 <= end; j += 4) {
        int2 e0 = __ldg(pgw + j),     e1 = __ldg(pgw + j + 1);
        int2 e2 = __ldg(pgw + j + 2), e3 = __ldg(pgw + j + 3);
        uint2 u0 = __ldg(fb + (size_t)e0.x * 32 + lane);
        uint2 u1 = __ldg(fb + (size_t)e1.x * 32 + lane);
        uint2 u2 = __ldg(fb + (size_t)e2.x * 32 + lane);
        uint2 u3 = __ldg(fb + (size_t)e3.x * 32 + lane);
        float w0 = __int_as_float(e0.y), w1 = __int_as_float(e1.y);
        float w2 = __int_as_float(e2.y), w3 = __int_as_float(e3.y);
#pragma unroll
        for (int q = 0; q < 4; q++) {
            uint2 u = (q == 0) ? u0 : (q == 1) ? u1 : (q == 2) ? u2 : u3;
            float w = (q == 0) ? w0 : (q == 1) ? w1 : (q == 2) ? w2 : w3;
            float2 f0 = __half22float2(*(__half2*)&u.x);
            float2 f1 = __half22float2(*(__half2*)&u.y);
            acc.x += f0.x * w; acc.y += f0.y * w;
            acc.z += f1.x * w; acc.w += f1.y * w;
        }
    }
    for (; j < end; j++) {
        int2 e = __ldg(pgw + j);
        float w = __int_as_float(e.y);
        uint2 u = __ldg(fb + (size_t)e.x * 32 + lane);
        float2 f0 = __half22float2(*(__half2*)&u.x);
        float2 f1 = __half22float2(*(__half2*)&u.y);
        acc.x += f0.x * w; acc.y += f0.y * w; acc.z += f1.x * w; acc.w += f1.y * w;
    }
    int deg = end - start;
    float inv = 1.0f / (deg > 1 ? (float)deg : 1.0f);
    float4 x = __ldg((const float4*)(xb + (size_t)n * DD) + lane);
    float4 r;
    r.x = (acc.x * inv + x.x) * 0.5f;
    r.y = (acc.y * inv + x.y) * 0.5f;
    r.z = (acc.z * inv + x.z) * 0.5f;
    r.w = (acc.w * inv + x.w) * 0.5f;
    __half2 h0 = __floats2half2_rn(r.x, r.y);
    __half2 h1 = __floats2half2_rn(r.z, r.w);
    uint2 o = make_uint2(*(unsigned*)&h0, *(unsigned*)&h1);
    ((uint2*)outh)[(size_t)n * 32 + lane] = o;
}

// ======== gather B: fp16 src, unweighted, out fp32 mean ========
__global__ void k_gather_s_h(const __half* __restrict__ feath,
                             const int*    __restrict__ pg,
                             const int*    __restrict__ rp,
                             float* __restrict__ out,
                             int N)
{
    int t = blockIdx.x * blockDim.x + threadIdx.x;
    int n = t >> 5, lane = t & 31;
    if (n >= N) return;
    int start = __ldg(rp + n), end = __ldg(rp + n + 1);
    const uint2* fb = (const uint2*)feath;   // 32 uint2 per row

    float4 acc = make_float4(0.f, 0.f, 0.f, 0.f);
    int j = start;
    for (; j + 4 <= end; j += 4) {
        int g0 = __ldg(pg + j), g1 = __ldg(pg + j + 1);
        int g2 = __ldg(pg + j + 2), g3 = __ldg(pg + j + 3);
        uint2 u0 = __ldg(fb + (size_t)g0 * 32 + lane);
        uint2 u1 = __ldg(fb + (size_t)g1 * 32 + lane);
        uint2 u2 = __ldg(fb + (size_t)g2 * 32 + lane);
        uint2 u3 = __ldg(fb + (size_t)g3 * 32 + lane);
#pragma unroll
        for (int q = 0; q < 4; q++) {
            uint2 u = (q == 0) ? u0 : (q == 1) ? u1 : (q == 2) ? u2 : u3;
            float2 f0 = __half22float2(*(__half2*)&u.x);
            float2 f1 = __half22float2(*(__half2*)&u.y);
            acc.x += f0.x; acc.y += f0.y; acc.z += f1.x; acc.w += f1.y;
        }
    }
    for (; j < end; j++) {
        int g = __ldg(pg + j);
        uint2 u = __ldg(fb + (size_t)g * 32 + lane);
        float2 f0 = __half22float2(*(__half2*)&u.x);
        float2 f1 = __half22float2(*(__half2*)&u.y);
        acc.x += f0.x; acc.y += f0.y; acc.z += f1.x; acc.w += f1.y;
    }
    int deg = end - start;
    float inv = 1.0f / (deg > 1 ? (float)deg : 1.0f);
    float4 o = make_float4(acc.x * inv, acc.y * inv, acc.z * inv, acc.w * inv);
    ((float4*)(out + (size_t)n * DD))[lane] = o;
}

// ======== gather C: fp16 src, unweighted, out = half((mean + xb)*0.5) ========
__global__ void k_gather_msg_hh(const __half* __restrict__ feath,
                                const int*    __restrict__ pg,
                                const int*    __restrict__ rp,
                                const float*  __restrict__ xb,
                                __half* __restrict__ outh,
                                int N)
{
    int t = blockIdx.x * blockDim.x + threadIdx.x;
    int n = t >> 5, lane = t & 31;
    if (n >= N) return;
    int start = __ldg(rp + n), end = __ldg(rp + n + 1);
    const uint2* fb = (const uint2*)feath;

    float4 acc = make_float4(0.f, 0.f, 0.f, 0.f);
    int j = start;
    for (; j + 4 <= end; j += 4) {
        int g0 = __ldg(pg + j), g1 = __ldg(pg + j + 1);
        int g2 = __ldg(pg + j + 2), g3 = __ldg(pg + j + 3);
        uint2 u0 = __ldg(fb + (size_t)g0 * 32 + lane);
        uint2 u1 = __ldg(fb + (size_t)g1 * 32 + lane);
        uint2 u2 = __ldg(fb + (size_t)g2 * 32 + lane);
        uint2 u3 = __ldg(fb + (size_t)g3 * 32 + lane);
#pragma unroll
        for (int q = 0; q < 4; q++) {
            uint2 u = (q == 0) ? u0 : (q == 1) ? u1 : (q == 2) ? u2 : u3;
            float2 f0 = __half22float2(*(__half2*)&u.x);
            float2 f1 = __half22float2(*(__half2*)&u.y);
            acc.x += f0.x; acc.y += f0.y; acc.z += f1.x; acc.w += f1.y;
        }
    }
    for (; j < end; j++) {
        int g = __ldg(pg + j);
        uint2 u = __ldg(fb + (size_t)g * 32 + lane);
        float2 f0 = __half22float2(*(__half2*)&u.x);
        float2 f1 = __half22float2(*(__half2*)&u.y);
        acc.x += f0.x; acc.y += f0.y; acc.z += f1.x; acc.w += f1.y;
    }
    int deg = end - start;
    float inv = 1.0f / (deg > 1 ? (float)deg : 1.0f);
    float4 x = __ldg((const float4*)(xb + (size_t)n * DD) + lane);
    float4 r;
    r.x = (acc.x * inv + x.x) * 0.5f;
    r.y = (acc.y * inv + x.y) * 0.5f;
    r.z = (acc.z * inv + x.z) * 0.5f;
    r.w = (acc.w * inv + x.w) * 0.5f;
    __half2 h0 = __floats2half2_rn(r.x, r.y);
    __half2 h1 = __floats2half2_rn(r.z, r.w);
    uint2 o = make_uint2(*(unsigned*)&h0, *(unsigned*)&h1);
    ((uint2*)outh)[(size_t)n * 32 + lane] = o;
}

// ======== dual gather: fp16 srcs, packed weight (b only), fp32 outs ========
__global__ void k_gather_dual_h(const __half* __restrict__ feat_a,
                                const __half* __restrict__ feat_b,
                                const int2*   __restrict__ pgw,
                                const int*    __restrict__ rp,
                                float* __restrict__ out_a,
                                float* __restrict__ out_b,
                                int N)
{
    int t = blockIdx.x * blockDim.x + threadIdx.x;
    int n = t >> 5, lane = t & 31;
    if (n >= N) return;
    int start = __ldg(rp + n), end = __ldg(rp + n + 1);
    const uint2* fa = (const uint2*)feat_a;
    const uint2* fbp = (const uint2*)feat_b;

    float4 aa = make_float4(0.f, 0.f, 0.f, 0.f);
    float4 ab = make_float4(0.f, 0.f, 0.f, 0.f);
    int j = start;
    for (; j + 2 <= end; j += 2) {
        int2 e0 = __ldg(pgw + j), e1 = __ldg(pgw + j + 1);
        uint2 a0 = __ldg(fa  + (size_t)e0.x * 32 + lane);
        uint2 b0 = __ldg(fbp + (size_t)e0.x * 32 + lane);
        uint2 a1 = __ldg(fa  + (size_t)e1.x * 32 + lane);
        uint2 b1 = __ldg(fbp + (size_t)e1.x * 32 + lane);
        float w0 = __int_as_float(e0.y), w1 = __int_as_float(e1.y);
        {
            float2 f0 = __half22float2(*(__half2*)&a0.x);
            float2 f1 = __half22float2(*(__half2*)&a0.y);
            float2 g0 = __half22float2(*(__half2*)&a1.x);
            float2 g1 = __half22float2(*(__half2*)&a1.y);
            aa.x += f0.x + g0.x; aa.y += f0.y + g0.y;
            aa.z += f1.x + g1.x; aa.w += f1.y + g1.y;
        }
        {
            float2 f0 = __half22float2(*(__half2*)&b0.x);
            float2 f1 = __half22float2(*(__half2*)&b0.y);
            float2 g0 = __half22float2(*(__half2*)&b1.x);
            float2 g1 = __half22float2(*(__half2*)&b1.y);
            ab.x += f0.x * w0 + g0.x * w1; ab.y += f0.y * w0 + g0.y * w1;
            ab.z += f1.x * w0 + g1.x * w1; ab.w += f1.y * w0 + g1.y * w1;
        }
    }
    for (; j < end; j++) {
        int2 e = __ldg(pgw + j);
        float w = __int_as_float(e.y);
        uint2 a = __ldg(fa  + (size_t)e.x * 32 + lane);
        uint2 b = __ldg(fbp + (size_t)e.x * 32 + lane);
        float2 f0 = __half22float2(*(__half2*)&a.x);
        float2 f1 = __half22float2(*(__half2*)&a.y);
        aa.x += f0.x; aa.y += f0.y; aa.z += f1.x; aa.w += f1.y;
        float2 h0 = __half22float2(*(__half2*)&b.x);
        float2 h1 = __half22float2(*(__half2*)&b.y);
        ab.x += h0.x * w; ab.y += h0.y * w; ab.z += h1.x * w; ab.w += h1.y * w;
    }
    int deg = end - start;
    float inv = 1.0f / (deg > 1 ? (float)deg : 1.0f);
    float4 oa = make_float4(aa.x * inv, aa.y * inv, aa.z * inv, aa.w * inv);
    float4 ob = make_float4(ab.x * inv, ab.y * inv, ab.z * inv, ab.w * inv);
    ((float4*)(out_a + (size_t)n * DD))[lane] = oa;
    ((float4*)(out_b + (size_t)n * DD))[lane] = ob;
}

// ---------------- GEMM (R4 version, unchanged): y = relu(x @ W^T + b), in place ----------------
#define GEMM_SMEM (64 * 128 * 4 + 129 * 128 * 4)

__device__ __forceinline__ void ffma2(unsigned long long& d, unsigned long long a,
                                      unsigned long long b) {
    asm("fma.rn.f32x2 %0, %1, %2, %0;" : "+l"(d) : "l"(a), "l"(b));
}
__device__ __forceinline__ unsigned long long pack2(float lo, float hi) {
    unsigned long long r;
    asm("mov.b64 %0, {%1, %2};" : "=l"(r) : "f"(lo), "f"(hi));
    return r;
}
__device__ __forceinline__ void unpack2(unsigned long long v, float& lo, float& hi) {
    asm("mov.b64 {%0, %1}, %2;" : "=f"(lo), "=f"(hi) : "l"(v));
}

__global__ void k_gemm_relu(float* __restrict__ xio,
                            const float* __restrict__ W,
                            const float* __restrict__ bias,
                            int N)
{
    extern __shared__ float sm[];
    float* xs = sm;              // [64][128]
    float* ws = sm + 64 * 128;   // [128][129] transposed W
    int tx = threadIdx.x, ty = threadIdx.y;
    int tid = ty * 32 + tx;
    int row0 = blockIdx.x * 64;

    for (int idx = tid; idx < 128 * 128; idx += 256) {
        int i = idx >> 7, k = idx & 127;
        ws[k * 129 + i] = __ldg(W + idx);
    }
    for (int idx = tid; idx < 64 * 32; idx += 256) {
        int r = idx >> 5;
        int row = row0 + r;
        float4 v = make_float4(0.f, 0.f, 0.f, 0.f);
        if (row < N) v = ((const float4*)(xio + (size_t)row * DD))[idx & 31];
        ((float4*)xs)[idx] = v;
    }
    __syncthreads();

    unsigned long long accA[8], accB[8];
#pragma unroll
    for (int r = 0; r < 8; r++) { accA[r] = 0ull; accB[r] = 0ull; }

#pragma unroll 4
    for (int k = 0; k < 128; k++) {
        float b0 = ws[k * 129 + tx];
        float b1 = ws[k * 129 + tx + 32];
        float b2 = ws[k * 129 + tx + 64];
        float b3 = ws[k * 129 + tx + 96];
        unsigned long long bA = pack2(b0, b1);
        unsigned long long bB = pack2(b2, b3);
#pragma unroll
        for (int r = 0; r < 8; r++) {
            float a = xs[(ty * 8 + r) * 128 + k];
            unsigned long long aa = pack2(a, a);
            ffma2(accA[r], aa, bA);
            ffma2(accB[r], aa, bB);
        }
    }

    float bb0 = __ldg(bias + tx);
    float bb1 = __ldg(bias + tx + 32);
    float bb2 = __ldg(bias + tx + 64);
    float bb3 = __ldg(bias + tx + 96);
#pragma unroll
    for (int r = 0; r < 8; r++) {
        int row = row0 + ty * 8 + r;
        if (row < N) {
            float a0, a1, a2, a3;
            unpack2(accA[r], a0, a1);
            unpack2(accB[r], a2, a3);
            float* yr = xio + (size_t)row * DD;
            yr[tx]      = fmaxf(a0 + bb0, 0.f);
            yr[tx + 32] = fmaxf(a1 + bb1, 0.f);
            yr[tx + 64] = fmaxf(a2 + bb2, 0.f);
            yr[tx + 96] = fmaxf(a3 + bb3, 0.f);
        }
    }
}

// ---------------- attention combine ----------------
__global__ void k_att(const float* __restrict__ y1,
                      const float* __restrict__ y2,
                      const float* __restrict__ y3,
                      const float* __restrict__ att,
                      float* __restrict__ out,
                      int N)
{
    int t = blockIdx.x * blockDim.x + threadIdx.x;
    int n = t >> 5, lane = t & 31;
    if (n >= N) return;
    size_t base = (size_t)n * DD;
    float4 v1 = __ldg((const float4*)(y1 + base) + lane);
    float4 v2 = __ldg((const float4*)(y2 + base) + lane);
    float4 v3 = __ldg((const float4*)(y3 + base) + lane);
    float4 a1 = __ldg((const float4*)att + lane);
    float4 a2 = __ldg((const float4*)att + 32 + lane);
    float4 a3 = __ldg((const float4*)att + 64 + lane);

    float s1 = v1.x * a1.x + v1.y * a1.y + v1.z * a1.z + v1.w * a1.w;
    float s2 = v2.x * a2.x + v2.y * a2.y + v2.z * a2.z + v2.w * a2.w;
    float s3 = v3.x * a3.x + v3.y * a3.y + v3.z * a3.z + v3.w * a3.w;
#pragma unroll
    for (int off = 16; off; off >>= 1) {
        s1 += __shfl_xor_sync(0xFFFFFFFFu, s1, off);
        s2 += __shfl_xor_sync(0xFFFFFFFFu, s2, off);
        s3 += __shfl_xor_sync(0xFFFFFFFFu, s3, off);
    }
    float m = fmaxf(s1, fmaxf(s2, s3));
    float e1 = __expf(s1 - m), e2 = __expf(s2 - m), e3 = __expf(s3 - m);
    float inv = 1.0f / (e1 + e2 + e3);
    float w1 = e1 * inv, w2 = e2 * inv, w3 = e3 * inv;

    float4 o;
    o.x = w1 * v1.x + w2 * v2.x + w3 * v3.x;
    o.y = w1 * v1.y + w2 * v2.y + w3 * v3.y;
    o.z = w1 * v1.z + w2 * v2.z + w3 * v3.z;
    o.w = w1 * v1.w + w2 * v2.w + w3 * v3.w;
    ((float4*)(out + base))[lane] = o;
}

// ---------------- launch ----------------
static inline int cdiv(long long a, int b) { return (int)((a + b - 1) / b); }

extern "C" void kernel_launch(void* const* d_in, const int* in_sizes, int n_in,
                              void* d_out, int out_size)
{
    const float* x_node   = (const float*)d_in[0];
    const float* x1       = (const float*)d_in[1];
    const float* x2       = (const float*)d_in[2];
    const int*   ei1_src  = (const int*)d_in[3];
    const int*   ei1_dst  = (const int*)d_in[4];
    const int*   ei2_src  = (const int*)d_in[5];
    const int*   ei2_dst  = (const int*)d_in[6];
    const int*   ei12_src = (const int*)d_in[7];
    const int*   ei12_dst = (const int*)d_in[8];
    const float* ew1      = (const float*)d_in[9];
    const float* ew2      = (const float*)d_in[10];
    const float* W1       = (const float*)d_in[11];
    const float* b1       = (const float*)d_in[12];
    const float* W2       = (const float*)d_in[13];
    const float* b2       = (const float*)d_in[14];
    const float* W12      = (const float*)d_in[15];
    const float* b12      = (const float*)d_in[16];
    const float* att      = (const float*)d_in[17];
    float* out = (float*)d_out;

    int n0  = in_sizes[0] / DD;
    int n1  = in_sizes[1] / DD;
    int n2  = in_sizes[2] / DD;
    int e1  = in_sizes[3];
    int e2  = in_sizes[5];
    int e12 = in_sizes[7];

    __half *xnodeh, *net1h, *net2h, *net2bh;
    float *s1, *s2, *s12;
    int *rowptr, *cursor, *pb1g, *pcg;
    int2 *p1gw, *p2gw, *pb2gw;
    cudaGetSymbolAddress((void**)&xnodeh, g_xnodeh);
    cudaGetSymbolAddress((void**)&net1h,  g_net1h);
    cudaGetSymbolAddress((void**)&net2h,  g_net2h);
    cudaGetSymbolAddress((void**)&net2bh, g_net2bh);
    cudaGetSymbolAddress((void**)&s1,  g_s1);
    cudaGetSymbolAddress((void**)&s2,  g_s2);
    cudaGetSymbolAddress((void**)&s12, g_s12);
    cudaGetSymbolAddress((void**)&rowptr, g_rowptr);
    cudaGetSymbolAddress((void**)&cursor, g_cursor);
    cudaGetSymbolAddress((void**)&p1gw,  g_p1gw);
    cudaGetSymbolAddress((void**)&p2gw,  g_p2gw);
    cudaGetSymbolAddress((void**)&pb2gw, g_pb2gw);
    cudaGetSymbolAddress((void**)&pb1g,  g_pb1g);
    cudaGetSymbolAddress((void**)&pcg,   g_pcg);

    cudaFuncSetAttribute(k_gemm_relu, cudaFuncAttributeMaxDynamicSharedMemorySize, GEMM_SMEM);

    cudaMemsetAsync(cursor, 0, (size_t)RPTOT * sizeof(int), 0);

    const int BT = 256;

    // --- x_node -> fp16 (overlaps with hist/scan/bin on same stream order) ---
    k_f2h<<<cdiv((long long)n0 * 32, BT), BT>>>(x_node, xnodeh, n0 * 32);

    // --- histograms ---
    k_hist<<<cdiv(e1, BT), BT>>>(ei1_dst,   cursor + RP1,  e1);
    k_hist<<<cdiv(e2, BT), BT>>>(ei2_dst,   cursor + RP2,  e2);
    k_hist<<<cdiv(e1, BT), BT>>>(ei1_src,   cursor + RPB1, e1);
    k_hist<<<cdiv(e12, BT), BT>>>(ei12_dst, cursor + RPC,  e12);
    k_hist<<<cdiv(e2, BT), BT>>>(ei2_src,   cursor + RPB2, e2);

    // --- fused scans ---
    Seg5 segs;
    segs.off[0] = RP1;  segs.n[0] = n1;
    segs.off[1] = RP2;  segs.n[1] = n2;
    segs.off[2] = RPB1; segs.n[2] = n0;
    segs.off[3] = RPC;  segs.n[3] = n2;
    segs.off[4] = RPB2; segs.n[4] = n0;
    k_scan5<<<5, 1024>>>(rowptr, cursor, segs);

    // --- binning ---
    k_bin_w<<<cdiv(e1, BT), BT>>>(ei1_dst,  ei1_src,  ew1, cursor + RP1,  p1gw,  e1);
    k_bin_w<<<cdiv(e2, BT), BT>>>(ei2_dst,  ei2_src,  ew2, cursor + RP2,  p2gw,  e2);
    k_bin_u<<<cdiv(e1, BT), BT>>>(ei1_src,  ei1_dst,  cursor + RPB1, pb1g, e1);
    k_bin_u<<<cdiv(e12, BT), BT>>>(ei12_dst, ei12_src, cursor + RPC,  pcg,  e12);
    k_bin_w<<<cdiv(e2, BT), BT>>>(ei2_src,  ei2_dst,  ew2, cursor + RPB2, pb2gw, e2);

    // --- gathers ---
    // net1h = half((mean(xnodeh[src]*ew1 by dst) + x1)*0.5)
    k_gather_msg_h16<<<cdiv((long long)n1 * 32, BT), BT>>>(xnodeh, p1gw, rowptr + RP1, x1, net1h, n1);
    // net2h likewise
    k_gather_msg_h16<<<cdiv((long long)n2 * 32, BT), BT>>>(xnodeh, p2gw, rowptr + RP2, x2, net2h, n2);
    // s1 = mean(net1h[dst] by src)  (fp32 out)
    k_gather_s_h<<<cdiv((long long)n0 * 32, BT), BT>>>(net1h, pb1g, rowptr + RPB1, s1, n0);
    // net2bh = half((mean(net1h[ei12_src] by ei12_dst) + x2)*0.5)
    k_gather_msg_hh<<<cdiv((long long)n2 * 32, BT), BT>>>(net1h, pcg, rowptr + RPC, x2, net2bh, n2);
    // s2 = mean(net2h); s12 = mean(net2bh*ew2)  (fp32 outs)
    k_gather_dual_h<<<cdiv((long long)n0 * 32, BT), BT>>>(net2h, net2bh, pb2gw, rowptr + RPB2, s2, s12, n0);

    // --- GEMM + ReLU (in place) ---
    dim3 gblk(32, 8);
    k_gemm_relu<<<cdiv(n0, 64), gblk, GEMM_SMEM>>>(s1,  W1,  b1,  n0);
    k_gemm_relu<<<cdiv(n0, 64), gblk, GEMM_SMEM>>>(s2,  W2,  b2,  n0);
    k_gemm_relu<<<cdiv(n0, 64), gblk, GEMM_SMEM>>>(s12, W12, b12, n0);

    // --- attention combine ---
    k_att<<<cdiv((long long)n0 * 32, BT), BT>>>(s1, s2, s12, att, out, n0);
}

// round 12
// speedup vs baseline: 1.7362x; 1.2455x over previous
#include <cuda_runtime.h>
#include <cuda_fp16.h>
#include <cstdint>
#include <math.h>

#define DD 128
#define N0CAP 100000
#define N1CAP 50000
#define N2CAP 50000
#define E1CAP 1600000
#define E2CAP 1600000
#define E12CAP 800000

// ---------------- scratch ----------------
__device__ __half g_xnodeh[N0CAP * DD];
__device__ __half g_net1h [N1CAP * DD];
__device__ __half g_net2h [N2CAP * DD];
__device__ __half g_net2bh[N2CAP * DD];
__device__ __half g_s1h[N0CAP * DD];
__device__ __half g_s2h[N0CAP * DD];
__device__ __half g_s12h[N0CAP * DD];
__device__ __half g_Wh[3 * DD * DD];
__device__ float  g_s1 [N0CAP * DD];
__device__ float  g_s2 [N0CAP * DD];
__device__ float  g_s12[N0CAP * DD];

#define RP1   0
#define RP2   (RP1 + N1CAP + 1)
#define RPB1  (RP2 + N2CAP + 1)
#define RPC   (RPB1 + N0CAP + 1)
#define RPB2  (RPC + N2CAP + 1)
#define RPTOT (RPB2 + N0CAP + 1)
__device__ int g_rowptr[RPTOT];
__device__ int g_cursor[RPTOT];   // doubles as histogram

__device__ int2 g_p1gw [E1CAP];   // (gather idx, weight bits)
__device__ int2 g_p2gw [E2CAP];
__device__ int2 g_pb2gw[E2CAP];
__device__ int  g_pb1g [E1CAP];
__device__ int  g_pcg  [E12CAP];

// ---------------- fp32 -> fp16 conversion (streaming) ----------------
__global__ void k_f2h(const float* __restrict__ src, __half* __restrict__ dst, int n4)
{
    int t = blockIdx.x * blockDim.x + threadIdx.x;
    if (t >= n4) return;
    float4 v = __ldg((const float4*)src + t);
    __half2 h0 = __floats2half2_rn(v.x, v.y);
    __half2 h1 = __floats2half2_rn(v.z, v.w);
    ((uint2*)dst)[t] = make_uint2(*(unsigned*)&h0, *(unsigned*)&h1);
}

// ---------------- histogram ----------------
__global__ void k_hist(const int* __restrict__ idx, int* __restrict__ hist, int E)
{
    int e = blockIdx.x * blockDim.x + threadIdx.x;
    if (e < E) atomicAdd(hist + __ldg(idx + e), 1);
}

// ---------------- fused exclusive scan over 5 segments ----------------
struct Seg5 { int off[5]; int n[5]; };
__global__ void k_scan5(int* __restrict__ rowptr_base, int* __restrict__ cur_base, Seg5 segs)
{
    __shared__ int wsum[32];
    int off = segs.off[blockIdx.x];
    int N   = segs.n[blockIdx.x];
    int* hist = cur_base + off;
    int* rp   = rowptr_base + off;

    int tid = threadIdx.x;                 // blockDim = 1024
    int per = (N + 1023) >> 10;
    int lo = tid * per; if (lo > N) lo = N;
    int hi = lo + per;  if (hi > N) hi = N;

    int sum = 0;
    for (int i = lo; i < hi; i++) sum += hist[i];

    int lane = tid & 31, wid = tid >> 5;
    int v = sum;
#pragma unroll
    for (int o = 1; o < 32; o <<= 1) {
        int t = __shfl_up_sync(0xffffffffu, v, o);
        if (lane >= o) v += t;
    }
    if (lane == 31) wsum[wid] = v;
    __syncthreads();
    if (wid == 0) {
        int s = wsum[lane];
#pragma unroll
        for (int o = 1; o < 32; o <<= 1) {
            int t = __shfl_up_sync(0xffffffffu, s, o);
            if (lane >= o) s += t;
        }
        wsum[lane] = s;
    }
    __syncthreads();
    int excl = (v - sum) + (wid ? wsum[wid - 1] : 0);

    int run = excl;
    for (int i = lo; i < hi; i++) {
        int c = hist[i];
        rp[i] = run;
        hist[i] = run;
        run += c;
    }
    if (tid == 1023) rp[N] = excl + sum;
}

// ---------------- binning ----------------
__global__ void k_bin_w(const int*   __restrict__ sc_idx,
                        const int*   __restrict__ g_idx,
                        const float* __restrict__ ew,
                        int*  __restrict__ cursor,
                        int2* __restrict__ pgw,
                        int E)
{
    int e = blockIdx.x * blockDim.x + threadIdx.x;
    if (e >= E) return;
    int b = __ldg(sc_idx + e);
    int p = atomicAdd(cursor + b, 1);
    pgw[p] = make_int2(__ldg(g_idx + e), __float_as_int(__ldg(ew + e)));
}

__global__ void k_bin_u(const int* __restrict__ sc_idx,
                        const int* __restrict__ g_idx,
                        int* __restrict__ cursor,
                        int* __restrict__ pg,
                        int E)
{
    int e = blockIdx.x * blockDim.x + threadIdx.x;
    if (e >= E) return;
    int b = __ldg(sc_idx + e);
    int p = atomicAdd(cursor + b, 1);
    pg[p] = __ldg(g_idx + e);
}

// ======== gather A: fp16 src, weighted(packed), out = half((mean + xb)*0.5) ========
__global__ void k_gather_msg_h16(const __half* __restrict__ feath,
                                 const int2*   __restrict__ pgw,
                                 const int*    __restrict__ rp,
                                 const float*  __restrict__ xb,
                                 __half* __restrict__ outh,
                                 int N)
{
    int t = blockIdx.x * blockDim.x + threadIdx.x;
    int n = t >> 5, lane = t & 31;
    if (n >= N) return;
    int start = __ldg(rp + n), end = __ldg(rp + n + 1);
    const uint2* fb = (const uint2*)feath;

    float4 acc = make_float4(0.f, 0.f, 0.f, 0.f);
    int j = start;
    for (; j + 4 <= end; j += 4) {
        int2 e0 = __ldg(pgw + j),     e1 = __ldg(pgw + j + 1);
        int2 e2 = __ldg(pgw + j + 2), e3 = __ldg(pgw + j + 3);
        uint2 u0 = __ldg(fb + (size_t)e0.x * 32 + lane);
        uint2 u1 = __ldg(fb + (size_t)e1.x * 32 + lane);
        uint2 u2 = __ldg(fb + (size_t)e2.x * 32 + lane);
        uint2 u3 = __ldg(fb + (size_t)e3.x * 32 + lane);
        float w0 = __int_as_float(e0.y), w1 = __int_as_float(e1.y);
        float w2 = __int_as_float(e2.y), w3 = __int_as_float(e3.y);
#pragma unroll
        for (int q = 0; q < 4; q++) {
            uint2 u = (q == 0) ? u0 : (q == 1) ? u1 : (q == 2) ? u2 : u3;
            float w = (q == 0) ? w0 : (q == 1) ? w1 : (q == 2) ? w2 : w3;
            float2 f0 = __half22float2(*(__half2*)&u.x);
            float2 f1 = __half22float2(*(__half2*)&u.y);
            acc.x += f0.x * w; acc.y += f0.y * w;
            acc.z += f1.x * w; acc.w += f1.y * w;
        }
    }
    for (; j < end; j++) {
        int2 e = __ldg(pgw + j);
        float w = __int_as_float(e.y);
        uint2 u = __ldg(fb + (size_t)e.x * 32 + lane);
        float2 f0 = __half22float2(*(__half2*)&u.x);
        float2 f1 = __half22float2(*(__half2*)&u.y);
        acc.x += f0.x * w; acc.y += f0.y * w; acc.z += f1.x * w; acc.w += f1.y * w;
    }
    int deg = end - start;
    float inv = 1.0f / (deg > 1 ? (float)deg : 1.0f);
    float4 x = __ldg((const float4*)(xb + (size_t)n * DD) + lane);
    float4 r;
    r.x = (acc.x * inv + x.x) * 0.5f;
    r.y = (acc.y * inv + x.y) * 0.5f;
    r.z = (acc.z * inv + x.z) * 0.5f;
    r.w = (acc.w * inv + x.w) * 0.5f;
    __half2 h0 = __floats2half2_rn(r.x, r.y);
    __half2 h1 = __floats2half2_rn(r.z, r.w);
    uint2 o = make_uint2(*(unsigned*)&h0, *(unsigned*)&h1);
    ((uint2*)outh)[(size_t)n * 32 + lane] = o;
}

// ======== gather B: fp16 src, unweighted, out = half(mean) ========
__global__ void k_gather_s_h(const __half* __restrict__ feath,
                             const int*    __restrict__ pg,
                             const int*    __restrict__ rp,
                             __half* __restrict__ outh,
                             int N)
{
    int t = blockIdx.x * blockDim.x + threadIdx.x;
    int n = t >> 5, lane = t & 31;
    if (n >= N) return;
    int start = __ldg(rp + n), end = __ldg(rp + n + 1);
    const uint2* fb = (const uint2*)feath;

    float4 acc = make_float4(0.f, 0.f, 0.f, 0.f);
    int j = start;
    for (; j + 4 <= end; j += 4) {
        int g0 = __ldg(pg + j), g1 = __ldg(pg + j + 1);
        int g2 = __ldg(pg + j + 2), g3 = __ldg(pg + j + 3);
        uint2 u0 = __ldg(fb + (size_t)g0 * 32 + lane);
        uint2 u1 = __ldg(fb + (size_t)g1 * 32 + lane);
        uint2 u2 = __ldg(fb + (size_t)g2 * 32 + lane);
        uint2 u3 = __ldg(fb + (size_t)g3 * 32 + lane);
#pragma unroll
        for (int q = 0; q < 4; q++) {
            uint2 u = (q == 0) ? u0 : (q == 1) ? u1 : (q == 2) ? u2 : u3;
            float2 f0 = __half22float2(*(__half2*)&u.x);
            float2 f1 = __half22float2(*(__half2*)&u.y);
            acc.x += f0.x; acc.y += f0.y; acc.z += f1.x; acc.w += f1.y;
        }
    }
    for (; j < end; j++) {
        int g = __ldg(pg + j);
        uint2 u = __ldg(fb + (size_t)g * 32 + lane);
        float2 f0 = __half22float2(*(__half2*)&u.x);
        float2 f1 = __half22float2(*(__half2*)&u.y);
        acc.x += f0.x; acc.y += f0.y; acc.z += f1.x; acc.w += f1.y;
    }
    int deg = end - start;
    float inv = 1.0f / (deg > 1 ? (float)deg : 1.0f);
    __half2 h0 = __floats2half2_rn(acc.x * inv, acc.y * inv);
    __half2 h1 = __floats2half2_rn(acc.z * inv, acc.w * inv);
    uint2 o = make_uint2(*(unsigned*)&h0, *(unsigned*)&h1);
    ((uint2*)outh)[(size_t)n * 32 + lane] = o;
}

// ======== gather C: fp16 src, unweighted, out = half((mean + xb)*0.5) ========
__global__ void k_gather_msg_hh(const __half* __restrict__ feath,
                                const int*    __restrict__ pg,
                                const int*    __restrict__ rp,
                                const float*  __restrict__ xb,
                                __half* __restrict__ outh,
                                int N)
{
    int t = blockIdx.x * blockDim.x + threadIdx.x;
    int n = t >> 5, lane = t & 31;
    if (n >= N) return;
    int start = __ldg(rp + n), end = __ldg(rp + n + 1);
    const uint2* fb = (const uint2*)feath;

    float4 acc = make_float4(0.f, 0.f, 0.f, 0.f);
    int j = start;
    for (; j + 4 <= end; j += 4) {
        int g0 = __ldg(pg + j), g1 = __ldg(pg + j + 1);
        int g2 = __ldg(pg + j + 2), g3 = __ldg(pg + j + 3);
        uint2 u0 = __ldg(fb + (size_t)g0 * 32 + lane);
        uint2 u1 = __ldg(fb + (size_t)g1 * 32 + lane);
        uint2 u2 = __ldg(fb + (size_t)g2 * 32 + lane);
        uint2 u3 = __ldg(fb + (size_t)g3 * 32 + lane);
#pragma unroll
        for (int q = 0; q < 4; q++) {
            uint2 u = (q == 0) ? u0 : (q == 1) ? u1 : (q == 2) ? u2 : u3;
            float2 f0 = __half22float2(*(__half2*)&u.x);
            float2 f1 = __half22float2(*(__half2*)&u.y);
            acc.x += f0.x; acc.y += f0.y; acc.z += f1.x; acc.w += f1.y;
        }
    }
    for (; j < end; j++) {
        int g = __ldg(pg + j);
        uint2 u = __ldg(fb + (size_t)g * 32 + lane);
        float2 f0 = __half22float2(*(__half2*)&u.x);
        float2 f1 = __half22float2(*(__half2*)&u.y);
        acc.x += f0.x; acc.y += f0.y; acc.z += f1.x; acc.w += f1.y;
    }
    int deg = end - start;
    float inv = 1.0f / (deg > 1 ? (float)deg : 1.0f);
    float4 x = __ldg((const float4*)(xb + (size_t)n * DD) + lane);
    float4 r;
    r.x = (acc.x * inv + x.x) * 0.5f;
    r.y = (acc.y * inv + x.y) * 0.5f;
    r.z = (acc.z * inv + x.z) * 0.5f;
    r.w = (acc.w * inv + x.w) * 0.5f;
    __half2 h0 = __floats2half2_rn(r.x, r.y);
    __half2 h1 = __floats2half2_rn(r.z, r.w);
    uint2 o = make_uint2(*(unsigned*)&h0, *(unsigned*)&h1);
    ((uint2*)outh)[(size_t)n * 32 + lane] = o;
}

// ======== dual gather: fp16 srcs, packed weight (b only), half outs ========
__global__ void k_gather_dual_h(const __half* __restrict__ feat_a,
                                const __half* __restrict__ feat_b,
                                const int2*   __restrict__ pgw,
                                const int*    __restrict__ rp,
                                __half* __restrict__ out_a,
                                __half* __restrict__ out_b,
                                int N)
{
    int t = blockIdx.x * blockDim.x + threadIdx.x;
    int n = t >> 5, lane = t & 31;
    if (n >= N) return;
    int start = __ldg(rp + n), end = __ldg(rp + n + 1);
    const uint2* fa = (const uint2*)feat_a;
    const uint2* fbp = (const uint2*)feat_b;

    float4 aa = make_float4(0.f, 0.f, 0.f, 0.f);
    float4 ab = make_float4(0.f, 0.f, 0.f, 0.f);
    int j = start;
    for (; j + 2 <= end; j += 2) {
        int2 e0 = __ldg(pgw + j), e1 = __ldg(pgw + j + 1);
        uint2 a0 = __ldg(fa  + (size_t)e0.x * 32 + lane);
        uint2 b0 = __ldg(fbp + (size_t)e0.x * 32 + lane);
        uint2 a1 = __ldg(fa  + (size_t)e1.x * 32 + lane);
        uint2 b1 = __ldg(fbp + (size_t)e1.x * 32 + lane);
        float w0 = __int_as_float(e0.y), w1 = __int_as_float(e1.y);
        {
            float2 f0 = __half22float2(*(__half2*)&a0.x);
            float2 f1 = __half22float2(*(__half2*)&a0.y);
            float2 g0 = __half22float2(*(__half2*)&a1.x);
            float2 g1 = __half22float2(*(__half2*)&a1.y);
            aa.x += f0.x + g0.x; aa.y += f0.y + g0.y;
            aa.z += f1.x + g1.x; aa.w += f1.y + g1.y;
        }
        {
            float2 f0 = __half22float2(*(__half2*)&b0.x);
            float2 f1 = __half22float2(*(__half2*)&b0.y);
            float2 g0 = __half22float2(*(__half2*)&b1.x);
            float2 g1 = __half22float2(*(__half2*)&b1.y);
            ab.x += f0.x * w0 + g0.x * w1; ab.y += f0.y * w0 + g0.y * w1;
            ab.z += f1.x * w0 + g1.x * w1; ab.w += f1.y * w0 + g1.y * w1;
        }
    }
    for (; j < end; j++) {
        int2 e = __ldg(pgw + j);
        float w = __int_as_float(e.y);
        uint2 a = __ldg(fa  + (size_t)e.x * 32 + lane);
        uint2 b = __ldg(fbp + (size_t)e.x * 32 + lane);
        float2 f0 = __half22float2(*(__half2*)&a.x);
        float2 f1 = __half22float2(*(__half2*)&a.y);
        aa.x += f0.x; aa.y += f0.y; aa.z += f1.x; aa.w += f1.y;
        float2 h0 = __half22float2(*(__half2*)&b.x);
        float2 h1 = __half22float2(*(__half2*)&b.y);
        ab.x += h0.x * w; ab.y += h0.y * w; ab.z += h1.x * w; ab.w += h1.y * w;
    }
    int deg = end - start;
    float inv = 1.0f / (deg > 1 ? (float)deg : 1.0f);
    __half2 ha0 = __floats2half2_rn(aa.x * inv, aa.y * inv);
    __half2 ha1 = __floats2half2_rn(aa.z * inv, aa.w * inv);
    __half2 hb0 = __floats2half2_rn(ab.x * inv, ab.y * inv);
    __half2 hb1 = __floats2half2_rn(ab.z * inv, ab.w * inv);
    ((uint2*)out_a)[(size_t)n * 32 + lane] = make_uint2(*(unsigned*)&ha0, *(unsigned*)&ha1);
    ((uint2*)out_b)[(size_t)n * 32 + lane] = make_uint2(*(unsigned*)&hb0, *(unsigned*)&hb1);
}

// ======== tensor-core GEMM: out_f32 = relu(xh @ Wh^T + b) ========
// block 256 thr (8 warps), tile M=128 x N=128, K=128. mma.m16n8k16 fp16->fp32.
// smem pitch 136 halfs (272B = 17*16B): ldmatrix phases conflict-free.
#define APITCH 136
#define MMA_SMEM (2 * 128 * APITCH * 2)

__device__ __forceinline__ unsigned smem_u32p(const void* p) {
    return (unsigned)__cvta_generic_to_shared(p);
}

__global__ void __launch_bounds__(256, 2)
k_gemm_mma(const __half* __restrict__ xh,
           const __half* __restrict__ Wh,     // [n][k] row-major
           const float* __restrict__ bias,
           float* __restrict__ out,
           int N)
{
    extern __shared__ __half smh[];
    __half* As = smh;                  // [128][APITCH]
    __half* Bs = smh + 128 * APITCH;   // [128][APITCH]
    int tid = threadIdx.x;
    int lane = tid & 31, wid = tid >> 5;
    int row0 = blockIdx.x * 128;

    // load W
    for (int i = tid; i < 128 * 16; i += 256) {
        int r = i >> 4, c = i & 15;
        uint4 v = *((const uint4*)(Wh + r * DD) + c);
        *(uint4*)(Bs + r * APITCH + c * 8) = v;
    }
    // load A tile
    for (int i = tid; i < 128 * 16; i += 256) {
        int r = i >> 4, c = i & 15;
        int row = row0 + r;
        uint4 v = make_uint4(0u, 0u, 0u, 0u);
        if (row < N) v = *((const uint4*)(xh + (size_t)row * DD) + c);
        *(uint4*)(As + r * APITCH + c * 8) = v;
    }
    __syncthreads();

    float d[16][4];
#pragma unroll
    for (int t = 0; t < 16; t++) { d[t][0] = d[t][1] = d[t][2] = d[t][3] = 0.f; }

    int wm = wid * 16;
    int qr = lane & 7, q = lane >> 3;

#pragma unroll
    for (int kk = 0; kk < 8; kk++) {
        // A fragment: q0:(m0-7,k0) q1:(m8-15,k0) q2:(m0-7,k8) q3:(m8-15,k8)
        int arow = wm + qr + (q & 1) * 8;
        int acol = kk * 16 + (q >> 1) * 8;
        unsigned a0, a1, a2, a3;
        {
            unsigned addr = smem_u32p(As + arow * APITCH + acol);
            asm volatile("ldmatrix.sync.aligned.m8n8.x4.shared.b16 {%0,%1,%2,%3}, [%4];"
                         : "=r"(a0), "=r"(a1), "=r"(a2), "=r"(a3) : "r"(addr));
        }
#pragma unroll
        for (int bt = 0; bt < 8; bt++) {
            // B (W[n][k] = col-major B, non-trans): q0:(n0-7,k0) q1:(n0-7,k8) q2:(n8-15,k0) q3:(n8-15,k8)
            int brow = bt * 16 + qr + (q >> 1) * 8;
            int bcol = kk * 16 + (q & 1) * 8;
            unsigned b0, b1, b2, b3;
            unsigned addr = smem_u32p(Bs + brow * APITCH + bcol);
            asm volatile("ldmatrix.sync.aligned.m8n8.x4.shared.b16 {%0,%1,%2,%3}, [%4];"
                         : "=r"(b0), "=r"(b1), "=r"(b2), "=r"(b3) : "r"(addr));
            float* dt0 = d[2 * bt];
            asm volatile("mma.sync.aligned.m16n8k16.row.col.f32.f16.f16.f32 "
                         "{%0,%1,%2,%3}, {%4,%5,%6,%7}, {%8,%9}, {%0,%1,%2,%3};"
                         : "+f"(dt0[0]), "+f"(dt0[1]), "+f"(dt0[2]), "+f"(dt0[3])
                         : "r"(a0), "r"(a1), "r"(a2), "r"(a3), "r"(b0), "r"(b1));
            float* dt1 = d[2 * bt + 1];
            asm volatile("mma.sync.aligned.m16n8k16.row.col.f32.f16.f16.f32 "
                         "{%0,%1,%2,%3}, {%4,%5,%6,%7}, {%8,%9}, {%0,%1,%2,%3};"
                         : "+f"(dt1[0]), "+f"(dt1[1]), "+f"(dt1[2]), "+f"(dt1[3])
                         : "r"(a0), "r"(a1), "r"(a2), "r"(a3), "r"(b2), "r"(b3));
        }
    }

    int r_lo = row0 + wm + (lane >> 2);
    int cbase = (lane & 3) * 2;
#pragma unroll
    for (int t = 0; t < 16; t++) {
        int col = t * 8 + cbase;
        float bb0 = __ldg(bias + col), bb1 = __ldg(bias + col + 1);
        if (r_lo < N) {
            float2 v = make_float2(fmaxf(d[t][0] + bb0, 0.f), fmaxf(d[t][1] + bb1, 0.f));
            *(float2*)(out + (size_t)r_lo * DD + col) = v;
        }
        if (r_lo + 8 < N) {
            float2 v = make_float2(fmaxf(d[t][2] + bb0, 0.f), fmaxf(d[t][3] + bb1, 0.f));
            *(float2*)(out + (size_t)(r_lo + 8) * DD + col) = v;
        }
    }
}

// ---------------- attention combine ----------------
__global__ void k_att(const float* __restrict__ y1,
                      const float* __restrict__ y2,
                      const float* __restrict__ y3,
                      const float* __restrict__ att,
                      float* __restrict__ out,
                      int N)
{
    int t = blockIdx.x * blockDim.x + threadIdx.x;
    int n = t >> 5, lane = t & 31;
    if (n >= N) return;
    size_t base = (size_t)n * DD;
    float4 v1 = __ldg((const float4*)(y1 + base) + lane);
    float4 v2 = __ldg((const float4*)(y2 + base) + lane);
    float4 v3 = __ldg((const float4*)(y3 + base) + lane);
    float4 a1 = __ldg((const float4*)att + lane);
    float4 a2 = __ldg((const float4*)att + 32 + lane);
    float4 a3 = __ldg((const float4*)att + 64 + lane);

    float s1 = v1.x * a1.x + v1.y * a1.y + v1.z * a1.z + v1.w * a1.w;
    float s2 = v2.x * a2.x + v2.y * a2.y + v2.z * a2.z + v2.w * a2.w;
    float s3 = v3.x * a3.x + v3.y * a3.y + v3.z * a3.z + v3.w * a3.w;
#pragma unroll
    for (int off = 16; off; off >>= 1) {
        s1 += __shfl_xor_sync(0xFFFFFFFFu, s1, off);
        s2 += __shfl_xor_sync(0xFFFFFFFFu, s2, off);
        s3 += __shfl_xor_sync(0xFFFFFFFFu, s3, off);
    }
    float m = fmaxf(s1, fmaxf(s2, s3));
    float e1 = __expf(s1 - m), e2 = __expf(s2 - m), e3 = __expf(s3 - m);
    float inv = 1.0f / (e1 + e2 + e3);
    float w1 = e1 * inv, w2 = e2 * inv, w3 = e3 * inv;

    float4 o;
    o.x = w1 * v1.x + w2 * v2.x + w3 * v3.x;
    o.y = w1 * v1.y + w2 * v2.y + w3 * v3.y;
    o.z = w1 * v1.z + w2 * v2.z + w3 * v3.z;
    o.w = w1 * v1.w + w2 * v2.w + w3 * v3.w;
    ((float4*)(out + base))[lane] = o;
}

// ---------------- launch ----------------
static inline int cdiv(long long a, int b) { return (int)((a + b - 1) / b); }

extern "C" void kernel_launch(void* const* d_in, const int* in_sizes, int n_in,
                              void* d_out, int out_size)
{
    const float* x_node   = (const float*)d_in[0];
    const float* x1       = (const float*)d_in[1];
    const float* x2       = (const float*)d_in[2];
    const int*   ei1_src  = (const int*)d_in[3];
    const int*   ei1_dst  = (const int*)d_in[4];
    const int*   ei2_src  = (const int*)d_in[5];
    const int*   ei2_dst  = (const int*)d_in[6];
    const int*   ei12_src = (const int*)d_in[7];
    const int*   ei12_dst = (const int*)d_in[8];
    const float* ew1      = (const float*)d_in[9];
    const float* ew2      = (const float*)d_in[10];
    const float* W1       = (const float*)d_in[11];
    const float* b1       = (const float*)d_in[12];
    const float* W2       = (const float*)d_in[13];
    const float* b2       = (const float*)d_in[14];
    const float* W12      = (const float*)d_in[15];
    const float* b12      = (const float*)d_in[16];
    const float* att      = (const float*)d_in[17];
    float* out = (float*)d_out;

    int n0  = in_sizes[0] / DD;
    int n1  = in_sizes[1] / DD;
    int n2  = in_sizes[2] / DD;
    int e1  = in_sizes[3];
    int e2  = in_sizes[5];
    int e12 = in_sizes[7];

    __half *xnodeh, *net1h, *net2h, *net2bh, *s1h, *s2h, *s12h, *Wh;
    float *s1, *s2, *s12;
    int *rowptr, *cursor, *pb1g, *pcg;
    int2 *p1gw, *p2gw, *pb2gw;
    cudaGetSymbolAddress((void**)&xnodeh, g_xnodeh);
    cudaGetSymbolAddress((void**)&net1h,  g_net1h);
    cudaGetSymbolAddress((void**)&net2h,  g_net2h);
    cudaGetSymbolAddress((void**)&net2bh, g_net2bh);
    cudaGetSymbolAddress((void**)&s1h,  g_s1h);
    cudaGetSymbolAddress((void**)&s2h,  g_s2h);
    cudaGetSymbolAddress((void**)&s12h, g_s12h);
    cudaGetSymbolAddress((void**)&Wh,   g_Wh);
    cudaGetSymbolAddress((void**)&s1,  g_s1);
    cudaGetSymbolAddress((void**)&s2,  g_s2);
    cudaGetSymbolAddress((void**)&s12, g_s12);
    cudaGetSymbolAddress((void**)&rowptr, g_rowptr);
    cudaGetSymbolAddress((void**)&cursor, g_cursor);
    cudaGetSymbolAddress((void**)&p1gw,  g_p1gw);
    cudaGetSymbolAddress((void**)&p2gw,  g_p2gw);
    cudaGetSymbolAddress((void**)&pb2gw, g_pb2gw);
    cudaGetSymbolAddress((void**)&pb1g,  g_pb1g);
    cudaGetSymbolAddress((void**)&pcg,   g_pcg);

    cudaFuncSetAttribute(k_gemm_mma, cudaFuncAttributeMaxDynamicSharedMemorySize, MMA_SMEM);

    cudaMemsetAsync(cursor, 0, (size_t)RPTOT * sizeof(int), 0);

    const int BT = 256;

    // --- conversions (x_node, W1/W2/W12) ---
    k_f2h<<<cdiv((long long)n0 * 32, BT), BT>>>(x_node, xnodeh, n0 * 32);
    k_f2h<<<cdiv(DD * DD / 4, BT), BT>>>(W1,  Wh,                 DD * DD / 4);
    k_f2h<<<cdiv(DD * DD / 4, BT), BT>>>(W2,  Wh + DD * DD,       DD * DD / 4);
    k_f2h<<<cdiv(DD * DD / 4, BT), BT>>>(W12, Wh + 2 * DD * DD,   DD * DD / 4);

    // --- histograms ---
    k_hist<<<cdiv(e1, BT), BT>>>(ei1_dst,   cursor + RP1,  e1);
    k_hist<<<cdiv(e2, BT), BT>>>(ei2_dst,   cursor + RP2,  e2);
    k_hist<<<cdiv(e1, BT), BT>>>(ei1_src,   cursor + RPB1, e1);
    k_hist<<<cdiv(e12, BT), BT>>>(ei12_dst, cursor + RPC,  e12);
    k_hist<<<cdiv(e2, BT), BT>>>(ei2_src,   cursor + RPB2, e2);

    // --- fused scans ---
    Seg5 segs;
    segs.off[0] = RP1;  segs.n[0] = n1;
    segs.off[1] = RP2;  segs.n[1] = n2;
    segs.off[2] = RPB1; segs.n[2] = n0;
    segs.off[3] = RPC;  segs.n[3] = n2;
    segs.off[4] = RPB2; segs.n[4] = n0;
    k_scan5<<<5, 1024>>>(rowptr, cursor, segs);

    // --- binning ---
    k_bin_w<<<cdiv(e1, BT), BT>>>(ei1_dst,  ei1_src,  ew1, cursor + RP1,  p1gw,  e1);
    k_bin_w<<<cdiv(e2, BT), BT>>>(ei2_dst,  ei2_src,  ew2, cursor + RP2,  p2gw,  e2);
    k_bin_u<<<cdiv(e1, BT), BT>>>(ei1_src,  ei1_dst,  cursor + RPB1, pb1g, e1);
    k_bin_u<<<cdiv(e12, BT), BT>>>(ei12_dst, ei12_src, cursor + RPC,  pcg,  e12);
    k_bin_w<<<cdiv(e2, BT), BT>>>(ei2_src,  ei2_dst,  ew2, cursor + RPB2, pb2gw, e2);

    // --- gathers ---
    k_gather_msg_h16<<<cdiv((long long)n1 * 32, BT), BT>>>(xnodeh, p1gw, rowptr + RP1, x1, net1h, n1);
    k_gather_msg_h16<<<cdiv((long long)n2 * 32, BT), BT>>>(xnodeh, p2gw, rowptr + RP2, x2, net2h, n2);
    k_gather_s_h<<<cdiv((long long)n0 * 32, BT), BT>>>(net1h, pb1g, rowptr + RPB1, s1h, n0);
    k_gather_msg_hh<<<cdiv((long long)n2 * 32, BT), BT>>>(net1h, pcg, rowptr + RPC, x2, net2bh, n2);
    k_gather_dual_h<<<cdiv((long long)n0 * 32, BT), BT>>>(net2h, net2bh, pb2gw, rowptr + RPB2, s2h, s12h, n0);

    // --- tensor-core GEMM + bias + ReLU ---
    k_gemm_mma<<<cdiv(n0, 128), 256, MMA_SMEM>>>(s1h,  Wh,               b1,  s1,  n0);
    k_gemm_mma<<<cdiv(n0, 128), 256, MMA_SMEM>>>(s2h,  Wh + DD * DD,     b2,  s2,  n0);
    k_gemm_mma<<<cdiv(n0, 128), 256, MMA_SMEM>>>(s12h, Wh + 2 * DD * DD, b12, s12, n0);

    // --- attention combine ---
    k_att<<<cdiv((long long)n0 * 32, BT), BT>>>(s1, s2, s12, att, out, n0);
}